// round 2
// baseline (speedup 1.0000x reference)
#include <cuda_runtime.h>
#include <cstdint>
#include <cstddef>

#define NN    8192
#define INF_  512
#define OUTF  256
#define ALPHA 0.2f

// Scratch (device globals: no allocation allowed in kernel_launch)
__device__ float g_h[NN * OUTF];
__device__ float g_s1[NN];
__device__ float g_s2[NN];

typedef unsigned long long u64;

// ---- packed fp32x2 helpers (sm_100a) ----
__device__ __forceinline__ u64 pk2(float x, float y) {
    u64 r; asm("mov.b64 %0, {%1, %2};" : "=l"(r) : "f"(x), "f"(y)); return r;
}
__device__ __forceinline__ void upk2(u64 v, float &x, float &y) {
    asm("mov.b64 {%0, %1}, %2;" : "=f"(x), "=f"(y) : "l"(v));
}
__device__ __forceinline__ void fma2(u64 &d, u64 a, u64 b) {
    asm("fma.rn.f32x2 %0, %1, %2, %3;" : "=l"(d) : "l"(a), "l"(b), "l"(d));
}

// ============================================================
// Kernel 1: h = x @ W   (M=8192, K=512, N=256)
// Block: 32 rows x 256 cols, 128 threads, thread tile 16r x 4c.
// ============================================================
__global__ void __launch_bounds__(128) k_xw(const float* __restrict__ x,
                                            const float* __restrict__ W) {
    __shared__ __align__(16) float xs[32][36];    // [k][row], padded
    __shared__ __align__(16) float ws[32][256];   // [k][col]

    const int tid = threadIdx.x;
    const int i0  = blockIdx.x * 32;
    const int ty  = tid >> 6;    // 0..1  -> rows ty*16 .. +15
    const int tx  = tid & 63;    // 0..63 -> cols tx*4 .. +3

    u64 acc[8][4];
    #pragma unroll
    for (int r = 0; r < 8; r++)
        #pragma unroll
        for (int c = 0; c < 4; c++) acc[r][c] = 0ull;

    for (int k0 = 0; k0 < INF_; k0 += 32) {
        __syncthreads();
        // x tile: 32 rows x 32 k, transposed into xs[k][row]
        #pragma unroll
        for (int i = 0; i < 8; i++) {
            int idx = tid + i * 128;
            int kk = idx & 31, r = idx >> 5;
            xs[kk][r] = x[(size_t)(i0 + r) * INF_ + k0 + kk];
        }
        // W tile: 32 k x 256 cols (vectorized)
        #pragma unroll
        for (int i = 0; i < 16; i++) {
            int f4 = tid + i * 128;
            int kk = f4 >> 6; int c4 = (f4 & 63) << 2;
            *(float4*)&ws[kk][c4] = *(const float4*)&W[(size_t)(k0 + kk) * OUTF + c4];
        }
        __syncthreads();

        #pragma unroll 8
        for (int kk = 0; kk < 32; kk++) {
            const ulonglong2* xr = (const ulonglong2*)&xs[kk][ty * 16];
            ulonglong2 q0 = xr[0], q1 = xr[1], q2 = xr[2], q3 = xr[3];
            u64 xp[8] = {q0.x, q0.y, q1.x, q1.y, q2.x, q2.y, q3.x, q3.y};
            float4 wv = *(const float4*)&ws[kk][tx * 4];
            u64 w0 = pk2(wv.x, wv.x), w1 = pk2(wv.y, wv.y);
            u64 w2 = pk2(wv.z, wv.z), w3 = pk2(wv.w, wv.w);
            #pragma unroll
            for (int r = 0; r < 8; r++) {
                fma2(acc[r][0], xp[r], w0);
                fma2(acc[r][1], xp[r], w1);
                fma2(acc[r][2], xp[r], w2);
                fma2(acc[r][3], xp[r], w3);
            }
        }
    }

    // store h
    #pragma unroll
    for (int rp = 0; rp < 8; rp++) {
        int row_lo = ty * 16 + 2 * rp;
        float lx[4], hx[4];
        #pragma unroll
        for (int c = 0; c < 4; c++) upk2(acc[rp][c], lx[c], hx[c]);
        float4 o;
        o.x = lx[0]; o.y = lx[1]; o.z = lx[2]; o.w = lx[3];
        *(float4*)&g_h[(size_t)(i0 + row_lo) * OUTF + tx * 4] = o;
        o.x = hx[0]; o.y = hx[1]; o.z = hx[2]; o.w = hx[3];
        *(float4*)&g_h[(size_t)(i0 + row_lo + 1) * OUTF + tx * 4] = o;
    }
}

// ============================================================
// Kernel 2: s1 = h @ a[:256], s2 = h @ a[256:]
// One warp per row.
// ============================================================
__global__ void __launch_bounds__(256) k_s(const float* __restrict__ a) {
    int row  = blockIdx.x * 8 + (threadIdx.x >> 5);
    int lane = threadIdx.x & 31;
    const float* hr = g_h + (size_t)row * OUTF;
    float p1 = 0.f, p2 = 0.f;
    #pragma unroll
    for (int c = lane; c < OUTF; c += 32) {
        float hv = hr[c];
        p1 += hv * a[c];
        p2 += hv * a[OUTF + c];
    }
    #pragma unroll
    for (int off = 16; off; off >>= 1) {
        p1 += __shfl_xor_sync(0xffffffffu, p1, off);
        p2 += __shfl_xor_sync(0xffffffffu, p2, off);
    }
    if (lane == 0) { g_s1[row] = p1; g_s2[row] = p2; }
}

// ============================================================
// Kernel 3 (dominant): fused masked-softmax + P @ h
// Block: 32 output rows x 256 cols, 128 threads, thread tile 16r x 4c.
// Loops over j in tiles of 32: generate p on the fly, accumulate acc += p@h and Z.
// ============================================================
__global__ void __launch_bounds__(128) k_attn(const int* __restrict__ adj,
                                              const float* __restrict__ bias,
                                              float* __restrict__ out) {
    __shared__ __align__(16) float ps[32][36];    // [j_local][i_local], padded
    __shared__ __align__(16) float hs[32][256];   // [j_local][col]
    __shared__ float s1s[32];
    __shared__ float zs[32];

    const int tid  = threadIdx.x;
    const int i0   = blockIdx.x * 32;
    const int ty   = tid >> 6;    // 0..1  -> rows ty*16..+15
    const int tx   = tid & 63;    // 0..63 -> cols tx*4..+3
    const int lane = tid & 31;    // p-gen: j index within tile
    const int prow = (tid >> 5) * 8;  // p-gen: 8-row group

    if (tid < 32) s1s[tid] = g_s1[i0 + tid];

    u64 acc[8][4];
    #pragma unroll
    for (int r = 0; r < 8; r++)
        #pragma unroll
        for (int c = 0; c < 4; c++) acc[r][c] = 0ull;
    float zacc[8];
    #pragma unroll
    for (int rr = 0; rr < 8; rr++) zacc[rr] = 0.f;

    __syncthreads();

    for (int j0 = 0; j0 < NN; j0 += 32) {
        __syncthreads();  // protect previous iteration's smem reads
        // h tile: 32 x 256 floats (vectorized, L2-resident after first wave)
        #pragma unroll
        for (int i = 0; i < 16; i++) {
            int f4 = tid + i * 128;
            int k = f4 >> 6; int c4 = (f4 & 63) << 2;
            *(float4*)&hs[k][c4] = *(const float4*)&g_h[(size_t)(j0 + k) * OUTF + c4];
        }
        // p tile: p[i_local][j_local] = adj ? exp(leaky_relu(s1+s2)) : 0
        {
            float s2v = g_s2[j0 + lane];
            #pragma unroll
            for (int rr = 0; rr < 8; rr++) {
                int r = prow + rr;
                int aij = adj[(size_t)(i0 + r) * NN + j0 + lane];
                float v = s1s[r] + s2v;
                v = v > 0.f ? v : ALPHA * v;
                float p = (aij > 0) ? __expf(v) : 0.f;
                zacc[rr] += p;
                ps[lane][r] = p;
            }
        }
        __syncthreads();

        #pragma unroll 8
        for (int kk = 0; kk < 32; kk++) {
            const ulonglong2* pr = (const ulonglong2*)&ps[kk][ty * 16];
            ulonglong2 q0 = pr[0], q1 = pr[1], q2 = pr[2], q3 = pr[3];
            u64 pp[8] = {q0.x, q0.y, q1.x, q1.y, q2.x, q2.y, q3.x, q3.y};
            float4 hv = *(const float4*)&hs[kk][tx * 4];
            u64 h0 = pk2(hv.x, hv.x), h1 = pk2(hv.y, hv.y);
            u64 h2 = pk2(hv.z, hv.z), h3 = pk2(hv.w, hv.w);
            #pragma unroll
            for (int r = 0; r < 8; r++) {
                fma2(acc[r][0], pp[r], h0);
                fma2(acc[r][1], pp[r], h1);
                fma2(acc[r][2], pp[r], h2);
                fma2(acc[r][3], pp[r], h3);
            }
        }
    }

    // reduce Z across lanes (each warp owns rows prow..prow+7, lanes = distinct j)
    #pragma unroll
    for (int off = 16; off; off >>= 1)
        #pragma unroll
        for (int rr = 0; rr < 8; rr++)
            zacc[rr] += __shfl_xor_sync(0xffffffffu, zacc[rr], off);
    if (lane == 0)
        #pragma unroll
        for (int rr = 0; rr < 8; rr++) zs[prow + rr] = zacc[rr];
    __syncthreads();

    // epilogue: out = acc / Z + bias
    float4 b4 = *(const float4*)&bias[tx * 4];
    #pragma unroll
    for (int rp = 0; rp < 8; rp++) {
        int row_lo = ty * 16 + 2 * rp;
        float izlo = 1.0f / zs[row_lo];
        float izhi = 1.0f / zs[row_lo + 1];
        float lx[4], hx[4];
        #pragma unroll
        for (int c = 0; c < 4; c++) upk2(acc[rp][c], lx[c], hx[c]);
        float4 o;
        o.x = lx[0] * izlo + b4.x; o.y = lx[1] * izlo + b4.y;
        o.z = lx[2] * izlo + b4.z; o.w = lx[3] * izlo + b4.w;
        *(float4*)&out[(size_t)(i0 + row_lo) * OUTF + tx * 4] = o;
        o.x = hx[0] * izhi + b4.x; o.y = hx[1] * izhi + b4.y;
        o.z = hx[2] * izhi + b4.z; o.w = hx[3] * izhi + b4.w;
        *(float4*)&out[(size_t)(i0 + row_lo + 1) * OUTF + tx * 4] = o;
    }
}

// ============================================================
extern "C" void kernel_launch(void* const* d_in, const int* in_sizes, int n_in,
                              void* d_out, int out_size) {
    (void)in_sizes; (void)n_in; (void)out_size;
    const float* x    = (const float*)d_in[0];
    const int*   adj  = (const int*)  d_in[1];
    const float* W    = (const float*)d_in[2];
    const float* a    = (const float*)d_in[3];
    const float* bias = (const float*)d_in[4];
    float* out = (float*)d_out;

    k_xw  <<<NN / 32, 128>>>(x, W);
    k_s   <<<NN / 8, 256>>>(a);
    k_attn<<<NN / 32, 128>>>(adj, bias, out);
}

// round 4
// speedup vs baseline: 2.0986x; 2.0986x over previous
#include <cuda_runtime.h>
#include <cuda_bf16.h>
#include <cstdint>
#include <cstddef>

#define NN    8192
#define INF_  512
#define OUTF  256
#define ALPHA 0.2f

typedef unsigned long long u64;
typedef unsigned int u32;

// ---------------- scratch globals (no allocs allowed) ----------------
__device__ float g_h[NN * OUTF];
__device__ float g_s1[NN];
__device__ float g_s2[NN];
__device__ float g_e1p[NN];   // exp(s1)
__device__ float g_e1n[NN];   // exp(ALPHA*s1)
__device__ float g_e2p[NN];   // exp(s2)
__device__ float g_e2n[NN];   // exp(ALPHA*s2)
// h split to bf16 hi/lo, stored PRE-SWIZZLED in the attention B-tile layout:
// byte(j, n) = j*512 + (((n>>3) ^ (j&7))<<4) + (n&7)*2
__device__ __align__(16) unsigned char g_hhi[(size_t)NN * 512];
__device__ __align__(16) unsigned char g_hlo[(size_t)NN * 512];

// ---------------- packed fp32x2 helpers (k_xw) ----------------
__device__ __forceinline__ u64 pk2(float x, float y) {
    u64 r; asm("mov.b64 %0, {%1, %2};" : "=l"(r) : "f"(x), "f"(y)); return r;
}
__device__ __forceinline__ void upk2(u64 v, float &x, float &y) {
    asm("mov.b64 {%0, %1}, %2;" : "=f"(x), "=f"(y) : "l"(v));
}
__device__ __forceinline__ void fma2(u64 &d, u64 a, u64 b) {
    asm("fma.rn.f32x2 %0, %1, %2, %3;" : "=l"(d) : "l"(a), "l"(b), "l"(d));
}

// ---------------- mma / ldmatrix / cp.async helpers ----------------
__device__ __forceinline__ u32 smem_u32(const void* p) {
    u32 a;
    asm("{ .reg .u64 t; cvta.to.shared.u64 t, %1; cvt.u32.u64 %0, t; }"
        : "=r"(a) : "l"(p));
    return a;
}
__device__ __forceinline__ void ldsm4(u32* r, u32 addr) {
    asm volatile("ldmatrix.sync.aligned.m8n8.x4.shared.b16 {%0,%1,%2,%3}, [%4];"
                 : "=r"(r[0]), "=r"(r[1]), "=r"(r[2]), "=r"(r[3]) : "r"(addr));
}
__device__ __forceinline__ void ldsm4t(u32* r, u32 addr) {
    asm volatile("ldmatrix.sync.aligned.m8n8.x4.trans.shared.b16 {%0,%1,%2,%3}, [%4];"
                 : "=r"(r[0]), "=r"(r[1]), "=r"(r[2]), "=r"(r[3]) : "r"(addr));
}
__device__ __forceinline__ void mma16816(float* d, const u32* a, const u32* b) {
    asm volatile(
        "mma.sync.aligned.m16n8k16.row.col.f32.bf16.bf16.f32 "
        "{%0,%1,%2,%3}, {%4,%5,%6,%7}, {%8,%9}, {%0,%1,%2,%3};"
        : "+f"(d[0]), "+f"(d[1]), "+f"(d[2]), "+f"(d[3])
        : "r"(a[0]), "r"(a[1]), "r"(a[2]), "r"(a[3]), "r"(b[0]), "r"(b[1]));
}
__device__ __forceinline__ void cpa16(u32 dst, const void* src) {
    asm volatile("cp.async.cg.shared.global [%0], [%1], 16;"
                 :: "r"(dst), "l"(src) : "memory");
}
__device__ __forceinline__ void cpa_commit() {
    asm volatile("cp.async.commit_group;" ::: "memory");
}
__device__ __forceinline__ void cpa_wait1() {
    asm volatile("cp.async.wait_group 1;" ::: "memory");
}
__device__ __forceinline__ void cpa_wait0() {
    asm volatile("cp.async.wait_group 0;" ::: "memory");
}

// split two floats -> packed bf16x2 hi + bf16x2 residual
__device__ __forceinline__ void split2(float a, float b, u32 &hi, u32 &lo) {
    __nv_bfloat16 ha = __float2bfloat16_rn(a);
    __nv_bfloat16 hb = __float2bfloat16_rn(b);
    hi = (u32)__bfloat16_as_ushort(ha) | ((u32)__bfloat16_as_ushort(hb) << 16);
    float ra = a - __bfloat162float(ha);
    float rb = b - __bfloat162float(hb);
    __nv_bfloat16 la = __float2bfloat16_rn(ra);
    __nv_bfloat16 lb = __float2bfloat16_rn(rb);
    lo = (u32)__bfloat16_as_ushort(la) | ((u32)__bfloat16_as_ushort(lb) << 16);
}

// ============================================================
// Kernel 1: h = x @ W ; also emits bf16 hi/lo pre-swizzled copies
// ============================================================
__global__ void __launch_bounds__(128) k_xw(const float* __restrict__ x,
                                            const float* __restrict__ W) {
    __shared__ __align__(16) float xs[32][36];
    __shared__ __align__(16) float ws[32][256];

    const int tid = threadIdx.x;
    const int i0  = blockIdx.x * 32;
    const int ty  = tid >> 6;
    const int tx  = tid & 63;

    u64 acc[8][4];
    #pragma unroll
    for (int r = 0; r < 8; r++)
        #pragma unroll
        for (int c = 0; c < 4; c++) acc[r][c] = 0ull;

    for (int k0 = 0; k0 < INF_; k0 += 32) {
        __syncthreads();
        #pragma unroll
        for (int i = 0; i < 8; i++) {
            int idx = tid + i * 128;
            int kk = idx & 31, r = idx >> 5;
            xs[kk][r] = x[(size_t)(i0 + r) * INF_ + k0 + kk];
        }
        #pragma unroll
        for (int i = 0; i < 16; i++) {
            int f4 = tid + i * 128;
            int kk = f4 >> 6; int c4 = (f4 & 63) << 2;
            *(float4*)&ws[kk][c4] = *(const float4*)&W[(size_t)(k0 + kk) * OUTF + c4];
        }
        __syncthreads();

        #pragma unroll 8
        for (int kk = 0; kk < 32; kk++) {
            const ulonglong2* xr = (const ulonglong2*)&xs[kk][ty * 16];
            ulonglong2 q0 = xr[0], q1 = xr[1], q2 = xr[2], q3 = xr[3];
            u64 xp[8] = {q0.x, q0.y, q1.x, q1.y, q2.x, q2.y, q3.x, q3.y};
            float4 wv = *(const float4*)&ws[kk][tx * 4];
            u64 w0 = pk2(wv.x, wv.x), w1 = pk2(wv.y, wv.y);
            u64 w2 = pk2(wv.z, wv.z), w3 = pk2(wv.w, wv.w);
            #pragma unroll
            for (int r = 0; r < 8; r++) {
                fma2(acc[r][0], xp[r], w0);
                fma2(acc[r][1], xp[r], w1);
                fma2(acc[r][2], xp[r], w2);
                fma2(acc[r][3], xp[r], w3);
            }
        }
    }

    #pragma unroll
    for (int rp = 0; rp < 8; rp++) {
        int row_lo = ty * 16 + 2 * rp;
        float lx[4], hx[4];
        #pragma unroll
        for (int c = 0; c < 4; c++) upk2(acc[rp][c], lx[c], hx[c]);
        #pragma unroll
        for (int half = 0; half < 2; half++) {
            int j = i0 + row_lo + half;
            float* v = half ? hx : lx;
            float4 o; o.x = v[0]; o.y = v[1]; o.z = v[2]; o.w = v[3];
            *(float4*)&g_h[(size_t)j * OUTF + tx * 4] = o;
            // bf16 split + swizzled store (n0 = tx*4)
            u32 h01, l01, h23, l23;
            split2(v[0], v[1], h01, l01);
            split2(v[2], v[3], h23, l23);
            u32 off = (u32)j * 512u + ((((u32)(tx >> 1)) ^ ((u32)j & 7u)) << 4)
                    + ((u32)(tx & 1)) * 8u;
            *(u64*)(g_hhi + off) = (u64)h01 | ((u64)h23 << 32);
            *(u64*)(g_hlo + off) = (u64)l01 | ((u64)l23 << 32);
        }
    }
}

// ============================================================
// Kernel 2: s1/s2 + factorized exp tables
// ============================================================
__global__ void __launch_bounds__(256) k_s(const float* __restrict__ a) {
    int row  = blockIdx.x * 8 + (threadIdx.x >> 5);
    int lane = threadIdx.x & 31;
    const float* hr = g_h + (size_t)row * OUTF;
    float p1 = 0.f, p2 = 0.f;
    #pragma unroll
    for (int c = lane; c < OUTF; c += 32) {
        float hv = hr[c];
        p1 += hv * a[c];
        p2 += hv * a[OUTF + c];
    }
    #pragma unroll
    for (int off = 16; off; off >>= 1) {
        p1 += __shfl_xor_sync(0xffffffffu, p1, off);
        p2 += __shfl_xor_sync(0xffffffffu, p2, off);
    }
    if (lane == 0) {
        g_s1[row]  = p1;
        g_s2[row]  = p2;
        g_e1p[row] = __expf(p1);
        g_e1n[row] = __expf(ALPHA * p1);
        g_e2p[row] = __expf(p2);
        g_e2n[row] = __expf(ALPHA * p2);
    }
}

// ============================================================
// Kernel 3: fused masked-softmax + P@h, mma.sync bf16-split
//   CTA: M=64 rows x N=256 cols, 256 threads (8 warps, 2m x 4n).
//   K-tiles of 64 over j; double-buffered smem; cp.async for B.
// ============================================================
#define KT 64
// smem layout (bytes): zs[64] @0 ; A tiles @1024 (buf,split: 4 x 8KB);
// B tiles @33792 (buf,split: 4 x 32KB). total 164864.
#define SM_ZS   0
#define SM_A    1024
#define SM_B    33792
#define SMEM_ATTN 164864

__global__ void __launch_bounds__(256) k_attn(const int* __restrict__ adj,
                                              const float* __restrict__ bias,
                                              float* __restrict__ out) {
    extern __shared__ __align__(16) char smem[];
    const u32 sb = smem_u32(smem);
    const int tid  = threadIdx.x;
    const int lane = tid & 31;
    const int wid  = tid >> 5;
    const int wn   = wid & 3;          // n-warp: cols wn*64..+63
    const int wm   = wid >> 2;         // m-warp: rows wm*32..+31
    const int i0   = blockIdx.x * 64;

    // ---- A-producer role: thread -> (row ia, j-quad jq) ----
    const int ia = tid >> 2;           // 0..63
    const int jq = tid & 3;            // j offsets jq*16..+15
    const float s1v  = g_s1[i0 + ia];
    const float e1pv = g_e1p[i0 + ia];
    const float e1nv = g_e1n[i0 + ia];
    float zacc = 0.f;

    float acc[2][8][4];
    #pragma unroll
    for (int mi = 0; mi < 2; mi++)
        #pragma unroll
        for (int n8 = 0; n8 < 8; n8++)
            #pragma unroll
            for (int c = 0; c < 4; c++) acc[mi][n8][c] = 0.f;

    const int NTILE = NN / KT;   // 128

    // ---- producers (lambda-ish via macros) ----
    // produce A for tile tt into buffer bb
    #define PRODUCE_A(tt, bb)                                                    \
    {                                                                            \
        const int jbase = (tt) * KT + jq * 16;                                   \
        const size_t arow = (size_t)(i0 + ia) * NN + jbase;                      \
        char* Ah = smem + SM_A + (bb) * 16384;                                   \
        char* Al = Ah + 8192;                                                    \
        u32 hw[4], lw[4];                                                        \
        _Pragma("unroll")                                                        \
        for (int q = 0; q < 4; q++) {                                            \
            int4  av  = *(const int4*)(adj + arow + q * 4);                      \
            float4 s2q = *(const float4*)(g_s2  + jbase + q * 4);                \
            float4 p2q = *(const float4*)(g_e2p + jbase + q * 4);                \
            float4 n2q = *(const float4*)(g_e2n + jbase + q * 4);                \
            float p0 = (av.x > 0) ? ((s1v + s2q.x > 0.f) ? e1pv * p2q.x : e1nv * n2q.x) : 0.f; \
            float p1 = (av.y > 0) ? ((s1v + s2q.y > 0.f) ? e1pv * p2q.y : e1nv * n2q.y) : 0.f; \
            float p2 = (av.z > 0) ? ((s1v + s2q.z > 0.f) ? e1pv * p2q.z : e1nv * n2q.z) : 0.f; \
            float p3 = (av.w > 0) ? ((s1v + s2q.w > 0.f) ? e1pv * p2q.w : e1nv * n2q.w) : 0.f; \
            zacc += (p0 + p1) + (p2 + p3);                                       \
            int idx = (q & 1) * 2;                                               \
            split2(p0, p1, hw[idx], lw[idx]);                                    \
            split2(p2, p3, hw[idx + 1], lw[idx + 1]);                            \
            if (q & 1) {                                                         \
                u32 chunk = (u32)(jq * 2 + (q >> 1));                            \
                u32 soff = (u32)ia * 128u + ((chunk ^ ((u32)ia & 7u)) << 4);     \
                *(uint4*)(Ah + soff) = make_uint4(hw[0], hw[1], hw[2], hw[3]);   \
                *(uint4*)(Al + soff) = make_uint4(lw[0], lw[1], lw[2], lw[3]);   \
            }                                                                    \
        }                                                                        \
    }

    // issue B cp.async for tile tt into buffer bb (pre-swizzled global copies)
    #define PRODUCE_B(tt, bb)                                                    \
    {                                                                            \
        const u32 dstH = sb + SM_B + (u32)(bb) * 65536u;                         \
        const u32 dstL = dstH + 32768u;                                          \
        const size_t gof = (size_t)(tt) * 32768;                                 \
        _Pragma("unroll")                                                        \
        for (int it = 0; it < 8; it++) {                                         \
            u32 off = (u32)tid * 16u + (u32)it * 4096u;                          \
            cpa16(dstH + off, g_hhi + gof + off);                                \
            cpa16(dstL + off, g_hlo + gof + off);                                \
        }                                                                        \
        cpa_commit();                                                            \
    }

    // ---- prologue ----
    PRODUCE_A(0, 0);
    PRODUCE_B(0, 0);

    // precomputed frag address pieces
    const u32 a_row_off = (u32)((wm * 32 + (lane & 15)) * 128);
    const u32 a_hi      = (u32)(lane >> 4);
    const u32 sxor      = (u32)(lane & 7);
    const u32 b_row_off = (u32)((lane & 15) * 512 + wn * 128);

    for (int t = 0; t < NTILE; t++) {
        const int buf = t & 1;
        if (t + 1 < NTILE) {
            PRODUCE_A(t + 1, buf ^ 1);
            PRODUCE_B(t + 1, buf ^ 1);
            cpa_wait1();
        } else {
            cpa_wait0();
        }
        __syncthreads();

        const u32 Abuf = sb + SM_A + (u32)buf * 16384u;
        const u32 Bbuf = sb + SM_B + (u32)buf * 65536u;

        #pragma unroll
        for (int split = 0; split < 3; split++) {
            const u32 Ab = Abuf + (split == 1 ? 8192u : 0u);
            const u32 Bb = Bbuf + (split == 2 ? 32768u : 0u);
            #pragma unroll
            for (int kk = 0; kk < 4; kk++) {
                u32 afr[2][4];
                #pragma unroll
                for (int mi = 0; mi < 2; mi++) {
                    u32 chunk = (u32)(kk * 2) + a_hi;
                    ldsm4(afr[mi], Ab + a_row_off + (u32)mi * 2048u
                                      + ((chunk ^ sxor) << 4));
                }
                u32 bfr[4][4];
                #pragma unroll
                for (int nb2 = 0; nb2 < 4; nb2++) {
                    u32 chunk = (u32)(nb2 * 2) + a_hi;
                    ldsm4t(bfr[nb2], Bb + (u32)(kk * 16) * 512u + b_row_off
                                        + ((chunk ^ sxor) << 4));
                }
                #pragma unroll
                for (int mi = 0; mi < 2; mi++)
                    #pragma unroll
                    for (int n8 = 0; n8 < 8; n8++)
                        mma16816(acc[mi][n8], afr[mi], &bfr[n8 >> 1][(n8 & 1) * 2]);
            }
        }
        __syncthreads();
    }

    // ---- Z reduce: 4 threads (adjacent lanes) per row ----
    zacc += __shfl_xor_sync(0xffffffffu, zacc, 1);
    zacc += __shfl_xor_sync(0xffffffffu, zacc, 2);
    float* zs = (float*)(smem + SM_ZS);
    if ((tid & 3) == 0) zs[ia] = zacc;
    __syncthreads();

    // ---- epilogue: out = acc/Z + bias ----
    const int g  = lane >> 2;
    const int tq = lane & 3;
    #pragma unroll
    for (int mi = 0; mi < 2; mi++) {
        int rl0 = wm * 32 + mi * 16 + g;
        float z0 = zs[rl0], z8 = zs[rl0 + 8];
        float inv0 = (z0 > 0.f) ? 1.0f / z0 : 0.f;
        float inv8 = (z8 > 0.f) ? 1.0f / z8 : 0.f;
        float* o0 = out + (size_t)(i0 + rl0) * OUTF;
        float* o8 = out + (size_t)(i0 + rl0 + 8) * OUTF;
        #pragma unroll
        for (int n8 = 0; n8 < 8; n8++) {
            int col = wn * 64 + n8 * 8 + tq * 2;
            float2 b2 = *(const float2*)(bias + col);
            float2 r0, r8;
            r0.x = acc[mi][n8][0] * inv0 + b2.x;
            r0.y = acc[mi][n8][1] * inv0 + b2.y;
            r8.x = acc[mi][n8][2] * inv8 + b2.x;
            r8.y = acc[mi][n8][3] * inv8 + b2.y;
            *(float2*)(o0 + col) = r0;
            *(float2*)(o8 + col) = r8;
        }
    }
    #undef PRODUCE_A
    #undef PRODUCE_B
}

// ============================================================
extern "C" void kernel_launch(void* const* d_in, const int* in_sizes, int n_in,
                              void* d_out, int out_size) {
    (void)in_sizes; (void)n_in; (void)out_size;
    const float* x    = (const float*)d_in[0];
    const int*   adj  = (const int*)  d_in[1];
    const float* W    = (const float*)d_in[2];
    const float* a    = (const float*)d_in[3];
    const float* bias = (const float*)d_in[4];
    float* out = (float*)d_out;

    cudaFuncSetAttribute(k_attn, cudaFuncAttributeMaxDynamicSharedMemorySize, SMEM_ATTN);

    k_xw  <<<NN / 32, 128>>>(x, W);
    k_s   <<<NN / 8, 256>>>(a);
    k_attn<<<NN / 64, 256, SMEM_ATTN>>>(adj, bias, out);
}

// round 5
// speedup vs baseline: 2.9604x; 1.4106x over previous
#include <cuda_runtime.h>
#include <cuda_bf16.h>
#include <cuda_fp16.h>
#include <cstdint>
#include <cstddef>

#define NN    8192
#define INF_  512
#define OUTF  256
#define ALPHA 0.2f

typedef unsigned long long u64;
typedef unsigned int u32;

// ---------------- scratch globals (no allocs allowed) ----------------
__device__ float g_h[NN * OUTF];
__device__ float g_s1[NN];
__device__ float g_s2[NN];
__device__ float g_e1p[NN];   // exp(s1)
__device__ float g_e1n[NN];   // exp(ALPHA*s1)
__device__ float g_e2p[NN];   // exp(s2)
__device__ float g_e2n[NN];   // exp(ALPHA*s2)
// h as fp16, stored PRE-SWIZZLED in the attention B-tile layout:
// byte(j, n) = j*512 + (((n>>3) ^ (j&7))<<4) + (n&7)*2
__device__ __align__(16) unsigned char g_hh[(size_t)NN * 512];

// ---------------- packed fp32x2 helpers (k_xw) ----------------
__device__ __forceinline__ u64 pk2(float x, float y) {
    u64 r; asm("mov.b64 %0, {%1, %2};" : "=l"(r) : "f"(x), "f"(y)); return r;
}
__device__ __forceinline__ void upk2(u64 v, float &x, float &y) {
    asm("mov.b64 {%0, %1}, %2;" : "=f"(x), "=f"(y) : "l"(v));
}
__device__ __forceinline__ void fma2(u64 &d, u64 a, u64 b) {
    asm("fma.rn.f32x2 %0, %1, %2, %3;" : "=l"(d) : "l"(a), "l"(b), "l"(d));
}

// ---------------- mma / ldmatrix / cp.async helpers ----------------
__device__ __forceinline__ u32 smem_u32(const void* p) {
    u32 a;
    asm("{ .reg .u64 t; cvta.to.shared.u64 t, %1; cvt.u32.u64 %0, t; }"
        : "=r"(a) : "l"(p));
    return a;
}
__device__ __forceinline__ void ldsm4(u32* r, u32 addr) {
    asm volatile("ldmatrix.sync.aligned.m8n8.x4.shared.b16 {%0,%1,%2,%3}, [%4];"
                 : "=r"(r[0]), "=r"(r[1]), "=r"(r[2]), "=r"(r[3]) : "r"(addr));
}
__device__ __forceinline__ void ldsm4t(u32* r, u32 addr) {
    asm volatile("ldmatrix.sync.aligned.m8n8.x4.trans.shared.b16 {%0,%1,%2,%3}, [%4];"
                 : "=r"(r[0]), "=r"(r[1]), "=r"(r[2]), "=r"(r[3]) : "r"(addr));
}
__device__ __forceinline__ void mma16816(float* d, const u32* a, const u32* b) {
    asm volatile(
        "mma.sync.aligned.m16n8k16.row.col.f32.f16.f16.f32 "
        "{%0,%1,%2,%3}, {%4,%5,%6,%7}, {%8,%9}, {%0,%1,%2,%3};"
        : "+f"(d[0]), "+f"(d[1]), "+f"(d[2]), "+f"(d[3])
        : "r"(a[0]), "r"(a[1]), "r"(a[2]), "r"(a[3]), "r"(b[0]), "r"(b[1]));
}
__device__ __forceinline__ void cpa16(u32 dst, const void* src) {
    asm volatile("cp.async.cg.shared.global [%0], [%1], 16;"
                 :: "r"(dst), "l"(src) : "memory");
}
__device__ __forceinline__ void cpa_commit() {
    asm volatile("cp.async.commit_group;" ::: "memory");
}
__device__ __forceinline__ void cpa_wait1() {
    asm volatile("cp.async.wait_group 1;" ::: "memory");
}
__device__ __forceinline__ void cpa_wait0() {
    asm volatile("cp.async.wait_group 0;" ::: "memory");
}
__device__ __forceinline__ u32 packh2(float a, float b) {
    __half2 h = __floats2half2_rn(a, b);
    return *reinterpret_cast<u32*>(&h);
}

// ============================================================
// Kernel 1: h = x @ W ; also emits fp16 pre-swizzled copy
// ============================================================
__global__ void __launch_bounds__(128) k_xw(const float* __restrict__ x,
                                            const float* __restrict__ W) {
    __shared__ __align__(16) float xs[32][36];
    __shared__ __align__(16) float ws[32][256];

    const int tid = threadIdx.x;
    const int i0  = blockIdx.x * 32;
    const int ty  = tid >> 6;
    const int tx  = tid & 63;

    u64 acc[8][4];
    #pragma unroll
    for (int r = 0; r < 8; r++)
        #pragma unroll
        for (int c = 0; c < 4; c++) acc[r][c] = 0ull;

    for (int k0 = 0; k0 < INF_; k0 += 32) {
        __syncthreads();
        #pragma unroll
        for (int i = 0; i < 8; i++) {
            int idx = tid + i * 128;
            int kk = idx & 31, r = idx >> 5;
            xs[kk][r] = x[(size_t)(i0 + r) * INF_ + k0 + kk];
        }
        #pragma unroll
        for (int i = 0; i < 16; i++) {
            int f4 = tid + i * 128;
            int kk = f4 >> 6; int c4 = (f4 & 63) << 2;
            *(float4*)&ws[kk][c4] = *(const float4*)&W[(size_t)(k0 + kk) * OUTF + c4];
        }
        __syncthreads();

        #pragma unroll 8
        for (int kk = 0; kk < 32; kk++) {
            const ulonglong2* xr = (const ulonglong2*)&xs[kk][ty * 16];
            ulonglong2 q0 = xr[0], q1 = xr[1], q2 = xr[2], q3 = xr[3];
            u64 xp[8] = {q0.x, q0.y, q1.x, q1.y, q2.x, q2.y, q3.x, q3.y};
            float4 wv = *(const float4*)&ws[kk][tx * 4];
            u64 w0 = pk2(wv.x, wv.x), w1 = pk2(wv.y, wv.y);
            u64 w2 = pk2(wv.z, wv.z), w3 = pk2(wv.w, wv.w);
            #pragma unroll
            for (int r = 0; r < 8; r++) {
                fma2(acc[r][0], xp[r], w0);
                fma2(acc[r][1], xp[r], w1);
                fma2(acc[r][2], xp[r], w2);
                fma2(acc[r][3], xp[r], w3);
            }
        }
    }

    #pragma unroll
    for (int rp = 0; rp < 8; rp++) {
        int row_lo = ty * 16 + 2 * rp;
        float lx[4], hx[4];
        #pragma unroll
        for (int c = 0; c < 4; c++) upk2(acc[rp][c], lx[c], hx[c]);
        #pragma unroll
        for (int half = 0; half < 2; half++) {
            int j = i0 + row_lo + half;
            float* v = half ? hx : lx;
            float4 o; o.x = v[0]; o.y = v[1]; o.z = v[2]; o.w = v[3];
            *(float4*)&g_h[(size_t)j * OUTF + tx * 4] = o;
            u32 h01 = packh2(v[0], v[1]);
            u32 h23 = packh2(v[2], v[3]);
            u32 off = (u32)j * 512u + ((((u32)(tx >> 1)) ^ ((u32)j & 7u)) << 4)
                    + ((u32)(tx & 1)) * 8u;
            *(u64*)(g_hh + off) = (u64)h01 | ((u64)h23 << 32);
        }
    }
}

// ============================================================
// Kernel 2: s1/s2 + factorized exp tables
// ============================================================
__global__ void __launch_bounds__(256) k_s(const float* __restrict__ a) {
    int row  = blockIdx.x * 8 + (threadIdx.x >> 5);
    int lane = threadIdx.x & 31;
    const float* hr = g_h + (size_t)row * OUTF;
    float p1 = 0.f, p2 = 0.f;
    #pragma unroll
    for (int c = lane; c < OUTF; c += 32) {
        float hv = hr[c];
        p1 += hv * a[c];
        p2 += hv * a[OUTF + c];
    }
    #pragma unroll
    for (int off = 16; off; off >>= 1) {
        p1 += __shfl_xor_sync(0xffffffffu, p1, off);
        p2 += __shfl_xor_sync(0xffffffffu, p2, off);
    }
    if (lane == 0) {
        g_s1[row]  = p1;
        g_s2[row]  = p2;
        g_e1p[row] = __expf(p1);
        g_e1n[row] = __expf(ALPHA * p1);
        g_e2p[row] = __expf(p2);
        g_e2n[row] = __expf(ALPHA * p2);
    }
}

// ============================================================
// Kernel 3: fused masked-softmax + P@h, single fp16 mma.sync
//   CTA: M=64 x N=256, 256 threads (8 warps, 2m x 4n, warp 32x64).
//   K-tiles of 128 over j; double-buffered smem; cp.async for B.
// ============================================================
#define KT 128
// smem: zs[64] @0 ; A @1024 (2 buf x 16KB); B @33792 (2 buf x 64KB)
#define SM_ZS   0
#define SM_A    1024
#define SM_B    33792
#define SMEM_ATTN 164864

__global__ void __launch_bounds__(256) k_attn(const int* __restrict__ adj,
                                              const float* __restrict__ bias,
                                              float* __restrict__ out) {
    extern __shared__ __align__(16) char smem[];
    const u32 sb = smem_u32(smem);
    const int tid  = threadIdx.x;
    const int lane = tid & 31;
    const int wid  = tid >> 5;
    const int wn   = wid & 3;          // n-warp: cols wn*64..+63
    const int wm   = wid >> 2;         // m-warp: rows wm*32..+31
    const int i0   = blockIdx.x * 64;

    // ---- A-producer role: thread -> (row ia, 32-j segment jq) ----
    const int ia = tid >> 2;           // 0..63
    const int jq = tid & 3;            // j offsets jq*32..+31
    const float s1v  = g_s1[i0 + ia];
    const float e1pv = g_e1p[i0 + ia];
    const float e1nv = g_e1n[i0 + ia];
    float zacc = 0.f;

    float acc[2][8][4];
    #pragma unroll
    for (int mi = 0; mi < 2; mi++)
        #pragma unroll
        for (int n8 = 0; n8 < 8; n8++)
            #pragma unroll
            for (int c = 0; c < 4; c++) acc[mi][n8][c] = 0.f;

    const int NTILE = NN / KT;   // 64

    // produce A (P fp16 tile [64 x 128]) for tile tt into buffer bb
    #define PRODUCE_A(tt, bb)                                                    \
    {                                                                            \
        const int jbase = (tt) * KT + jq * 32;                                   \
        const size_t arow = (size_t)(i0 + ia) * NN + jbase;                      \
        char* Ah = smem + SM_A + (bb) * 16384;                                   \
        u32 w[4];                                                                \
        _Pragma("unroll")                                                        \
        for (int q = 0; q < 8; q++) {                                            \
            int4   av  = *(const int4*)(adj + arow + q * 4);                     \
            float4 s2q = *(const float4*)(g_s2  + jbase + q * 4);                \
            float4 p2q = *(const float4*)(g_e2p + jbase + q * 4);                \
            float4 n2q = *(const float4*)(g_e2n + jbase + q * 4);                \
            float p0 = (av.x > 0) ? ((s1v + s2q.x > 0.f) ? e1pv * p2q.x : e1nv * n2q.x) : 0.f; \
            float p1 = (av.y > 0) ? ((s1v + s2q.y > 0.f) ? e1pv * p2q.y : e1nv * n2q.y) : 0.f; \
            float p2 = (av.z > 0) ? ((s1v + s2q.z > 0.f) ? e1pv * p2q.z : e1nv * n2q.z) : 0.f; \
            float p3 = (av.w > 0) ? ((s1v + s2q.w > 0.f) ? e1pv * p2q.w : e1nv * n2q.w) : 0.f; \
            zacc += (p0 + p1) + (p2 + p3);                                       \
            int idx = (q & 1) * 2;                                               \
            w[idx]     = packh2(p0, p1);                                         \
            w[idx + 1] = packh2(p2, p3);                                         \
            if (q & 1) {                                                         \
                u32 chunk = (u32)(jq * 4 + (q >> 1));                            \
                u32 soff = (u32)ia * 256u + ((chunk ^ ((u32)ia & 7u)) << 4);     \
                *(uint4*)(Ah + soff) = make_uint4(w[0], w[1], w[2], w[3]);       \
            }                                                                    \
        }                                                                        \
    }

    // issue B cp.async for tile tt into buffer bb (pre-swizzled fp16 h)
    #define PRODUCE_B(tt, bb)                                                    \
    {                                                                            \
        const u32 dst = sb + SM_B + (u32)(bb) * 65536u;                          \
        const size_t gof = (size_t)(tt) * 65536;                                 \
        _Pragma("unroll")                                                        \
        for (int it = 0; it < 16; it++) {                                        \
            u32 off = (u32)tid * 16u + (u32)it * 4096u;                          \
            cpa16(dst + off, g_hh + gof + off);                                  \
        }                                                                        \
        cpa_commit();                                                            \
    }

    // ---- prologue ----
    PRODUCE_A(0, 0);
    PRODUCE_B(0, 0);

    // frag address pieces
    const u32 a_row_off = (u32)((wm * 32 + (lane & 15)) * 256);
    const u32 a_hi      = (u32)(lane >> 4);
    const u32 sxor      = (u32)(lane & 7);
    const u32 b_row_off = (u32)((lane & 15) * 512 + wn * 128);

    for (int t = 0; t < NTILE; t++) {
        const int buf = t & 1;
        if (t + 1 < NTILE) {
            PRODUCE_A(t + 1, buf ^ 1);
            PRODUCE_B(t + 1, buf ^ 1);
            cpa_wait1();
        } else {
            cpa_wait0();
        }
        __syncthreads();

        const u32 Abuf = sb + SM_A + (u32)buf * 16384u;
        const u32 Bbuf = sb + SM_B + (u32)buf * 65536u;

        #pragma unroll
        for (int kk = 0; kk < 8; kk++) {
            u32 afr[2][4];
            #pragma unroll
            for (int mi = 0; mi < 2; mi++) {
                u32 chunk = (u32)(kk * 2) + a_hi;
                ldsm4(afr[mi], Abuf + a_row_off + (u32)mi * 4096u
                                  + ((chunk ^ sxor) << 4));
            }
            u32 bfr[4][4];
            #pragma unroll
            for (int nb2 = 0; nb2 < 4; nb2++) {
                u32 chunk = (u32)(nb2 * 2) + a_hi;
                ldsm4t(bfr[nb2], Bbuf + (u32)(kk * 16) * 512u + b_row_off
                                    + ((chunk ^ sxor) << 4));
            }
            #pragma unroll
            for (int mi = 0; mi < 2; mi++)
                #pragma unroll
                for (int n8 = 0; n8 < 8; n8++)
                    mma16816(acc[mi][n8], afr[mi], &bfr[n8 >> 1][(n8 & 1) * 2]);
        }
        __syncthreads();
    }

    // ---- Z reduce: 4 threads (adjacent lanes) per row ----
    zacc += __shfl_xor_sync(0xffffffffu, zacc, 1);
    zacc += __shfl_xor_sync(0xffffffffu, zacc, 2);
    float* zs = (float*)(smem + SM_ZS);
    if ((tid & 3) == 0) zs[ia] = zacc;
    __syncthreads();

    // ---- epilogue: out = acc/Z + bias ----
    const int g  = lane >> 2;
    const int tq = lane & 3;
    #pragma unroll
    for (int mi = 0; mi < 2; mi++) {
        int rl0 = wm * 32 + mi * 16 + g;
        float z0 = zs[rl0], z8 = zs[rl0 + 8];
        float inv0 = (z0 > 0.f) ? 1.0f / z0 : 0.f;
        float inv8 = (z8 > 0.f) ? 1.0f / z8 : 0.f;
        float* o0 = out + (size_t)(i0 + rl0) * OUTF;
        float* o8 = out + (size_t)(i0 + rl0 + 8) * OUTF;
        #pragma unroll
        for (int n8 = 0; n8 < 8; n8++) {
            int col = wn * 64 + n8 * 8 + tq * 2;
            float2 b2 = *(const float2*)(bias + col);
            float2 r0, r8;
            r0.x = acc[mi][n8][0] * inv0 + b2.x;
            r0.y = acc[mi][n8][1] * inv0 + b2.y;
            r8.x = acc[mi][n8][2] * inv8 + b2.x;
            r8.y = acc[mi][n8][3] * inv8 + b2.y;
            *(float2*)(o0 + col) = r0;
            *(float2*)(o8 + col) = r8;
        }
    }
    #undef PRODUCE_A
    #undef PRODUCE_B
}

// ============================================================
extern "C" void kernel_launch(void* const* d_in, const int* in_sizes, int n_in,
                              void* d_out, int out_size) {
    (void)in_sizes; (void)n_in; (void)out_size;
    const float* x    = (const float*)d_in[0];
    const int*   adj  = (const int*)  d_in[1];
    const float* W    = (const float*)d_in[2];
    const float* a    = (const float*)d_in[3];
    const float* bias = (const float*)d_in[4];
    float* out = (float*)d_out;

    cudaFuncSetAttribute(k_attn, cudaFuncAttributeMaxDynamicSharedMemorySize, SMEM_ATTN);

    k_xw  <<<NN / 32, 128>>>(x, W);
    k_s   <<<NN / 8, 256>>>(a);
    k_attn<<<NN / 64, 256, SMEM_ATTN>>>(adj, bias, out);
}

// round 6
// speedup vs baseline: 3.2142x; 1.0857x over previous
#include <cuda_runtime.h>
#include <cuda_bf16.h>
#include <cuda_fp16.h>
#include <cstdint>
#include <cstddef>

#define NN    8192
#define INF_  512
#define OUTF  256
#define ALPHA 0.2f

typedef unsigned long long u64;
typedef unsigned int u32;

// ---------------- scratch globals (no allocs allowed) ----------------
__device__ float g_h[NN * OUTF];
__device__ float g_s1[NN];
__device__ float g_s2[NN];
__device__ float g_e1p[NN];   // exp(s1)
__device__ float g_e1n[NN];   // exp(ALPHA*s1)
__device__ float g_e2p[NN];   // exp(s2)
__device__ float g_e2n[NN];   // exp(ALPHA*s2)
// h as fp16, PRE-SWIZZLED in the attention B-tile layout:
// byte(j, n) = j*512 + (((n>>3) ^ (j&7))<<4) + (n&7)*2
__device__ __align__(16) unsigned char g_hh[(size_t)NN * 512];

// ---------------- packed fp32x2 helpers (k_xw) ----------------
__device__ __forceinline__ u64 pk2(float x, float y) {
    u64 r; asm("mov.b64 %0, {%1, %2};" : "=l"(r) : "f"(x), "f"(y)); return r;
}
__device__ __forceinline__ void upk2(u64 v, float &x, float &y) {
    asm("mov.b64 {%0, %1}, %2;" : "=f"(x), "=f"(y) : "l"(v));
}
__device__ __forceinline__ void fma2(u64 &d, u64 a, u64 b) {
    asm("fma.rn.f32x2 %0, %1, %2, %3;" : "=l"(d) : "l"(a), "l"(b), "l"(d));
}

// ---------------- mma / ldmatrix / cp.async helpers ----------------
__device__ __forceinline__ u32 smem_u32(const void* p) {
    u32 a;
    asm("{ .reg .u64 t; cvta.to.shared.u64 t, %1; cvt.u32.u64 %0, t; }"
        : "=r"(a) : "l"(p));
    return a;
}
__device__ __forceinline__ void ldsm4(u32* r, u32 addr) {
    asm volatile("ldmatrix.sync.aligned.m8n8.x4.shared.b16 {%0,%1,%2,%3}, [%4];"
                 : "=r"(r[0]), "=r"(r[1]), "=r"(r[2]), "=r"(r[3]) : "r"(addr));
}
__device__ __forceinline__ void ldsm4t(u32* r, u32 addr) {
    asm volatile("ldmatrix.sync.aligned.m8n8.x4.trans.shared.b16 {%0,%1,%2,%3}, [%4];"
                 : "=r"(r[0]), "=r"(r[1]), "=r"(r[2]), "=r"(r[3]) : "r"(addr));
}
__device__ __forceinline__ void mma16816(float* d, const u32* a, const u32* b) {
    asm volatile(
        "mma.sync.aligned.m16n8k16.row.col.f32.f16.f16.f32 "
        "{%0,%1,%2,%3}, {%4,%5,%6,%7}, {%8,%9}, {%0,%1,%2,%3};"
        : "+f"(d[0]), "+f"(d[1]), "+f"(d[2]), "+f"(d[3])
        : "r"(a[0]), "r"(a[1]), "r"(a[2]), "r"(a[3]), "r"(b[0]), "r"(b[1]));
}
__device__ __forceinline__ void cpa16(u32 dst, const void* src) {
    asm volatile("cp.async.cg.shared.global [%0], [%1], 16;"
                 :: "r"(dst), "l"(src) : "memory");
}
__device__ __forceinline__ void cpa_commit() {
    asm volatile("cp.async.commit_group;" ::: "memory");
}
__device__ __forceinline__ void cpa_wait0() {
    asm volatile("cp.async.wait_group 0;" ::: "memory");
}
__device__ __forceinline__ u32 packh2(float a, float b) {
    __half2 h = __floats2half2_rn(a, b);
    return *reinterpret_cast<u32*>(&h);
}

// ============================================================
// Kernel 1: h = x @ W ; also emits fp16 pre-swizzled copy
//   256 threads, 32 rows/CTA, thread tile 8r x 4c (2x occupancy vs R5)
// ============================================================
__global__ void __launch_bounds__(256) k_xw(const float* __restrict__ x,
                                            const float* __restrict__ W) {
    __shared__ __align__(16) float xs[32][36];
    __shared__ __align__(16) float ws[32][256];

    const int tid = threadIdx.x;
    const int i0  = blockIdx.x * 32;
    const int ty  = tid >> 6;       // 0..3 -> rows ty*8 .. +7
    const int tx  = tid & 63;       // cols tx*4 .. +3

    u64 acc[4][4];
    #pragma unroll
    for (int r = 0; r < 4; r++)
        #pragma unroll
        for (int c = 0; c < 4; c++) acc[r][c] = 0ull;

    for (int k0 = 0; k0 < INF_; k0 += 32) {
        __syncthreads();
        #pragma unroll
        for (int i = 0; i < 4; i++) {
            int idx = tid + i * 256;
            int kk = idx & 31, r = idx >> 5;
            xs[kk][r] = x[(size_t)(i0 + r) * INF_ + k0 + kk];
        }
        #pragma unroll
        for (int i = 0; i < 8; i++) {
            int f4 = tid + i * 256;
            int kk = f4 >> 6; int c4 = (f4 & 63) << 2;
            *(float4*)&ws[kk][c4] = *(const float4*)&W[(size_t)(k0 + kk) * OUTF + c4];
        }
        __syncthreads();

        #pragma unroll 8
        for (int kk = 0; kk < 32; kk++) {
            const ulonglong2* xr = (const ulonglong2*)&xs[kk][ty * 8];
            ulonglong2 q0 = xr[0], q1 = xr[1];
            u64 xp[4] = {q0.x, q0.y, q1.x, q1.y};
            float4 wv = *(const float4*)&ws[kk][tx * 4];
            u64 w0 = pk2(wv.x, wv.x), w1 = pk2(wv.y, wv.y);
            u64 w2 = pk2(wv.z, wv.z), w3 = pk2(wv.w, wv.w);
            #pragma unroll
            for (int r = 0; r < 4; r++) {
                fma2(acc[r][0], xp[r], w0);
                fma2(acc[r][1], xp[r], w1);
                fma2(acc[r][2], xp[r], w2);
                fma2(acc[r][3], xp[r], w3);
            }
        }
    }

    #pragma unroll
    for (int rp = 0; rp < 4; rp++) {
        int row_lo = ty * 8 + 2 * rp;
        float lx[4], hx[4];
        #pragma unroll
        for (int c = 0; c < 4; c++) upk2(acc[rp][c], lx[c], hx[c]);
        #pragma unroll
        for (int half = 0; half < 2; half++) {
            int j = i0 + row_lo + half;
            float* v = half ? hx : lx;
            float4 o; o.x = v[0]; o.y = v[1]; o.z = v[2]; o.w = v[3];
            *(float4*)&g_h[(size_t)j * OUTF + tx * 4] = o;
            u32 h01 = packh2(v[0], v[1]);
            u32 h23 = packh2(v[2], v[3]);
            u32 off = (u32)j * 512u + ((((u32)(tx >> 1)) ^ ((u32)j & 7u)) << 4)
                    + ((u32)(tx & 1)) * 8u;
            *(u64*)(g_hh + off) = (u64)h01 | ((u64)h23 << 32);
        }
    }
}

// ============================================================
// Kernel 2: s1/s2 + factorized exp tables
// ============================================================
__global__ void __launch_bounds__(256) k_s(const float* __restrict__ a) {
    int row  = blockIdx.x * 8 + (threadIdx.x >> 5);
    int lane = threadIdx.x & 31;
    const float* hr = g_h + (size_t)row * OUTF;
    float p1 = 0.f, p2 = 0.f;
    #pragma unroll
    for (int c = lane; c < OUTF; c += 32) {
        float hv = hr[c];
        p1 += hv * a[c];
        p2 += hv * a[OUTF + c];
    }
    #pragma unroll
    for (int off = 16; off; off >>= 1) {
        p1 += __shfl_xor_sync(0xffffffffu, p1, off);
        p2 += __shfl_xor_sync(0xffffffffu, p2, off);
    }
    if (lane == 0) {
        g_s1[row]  = p1;
        g_s2[row]  = p2;
        g_e1p[row] = __expf(p1);
        g_e1n[row] = __expf(ALPHA * p1);
        g_e2p[row] = __expf(p2);
        g_e2n[row] = __expf(ALPHA * p2);
    }
}

// ============================================================
// Kernel 3: fused masked-softmax + P@h, fp16 mma.sync
//   CTA: M=64 x N=256, 256 threads (8 warps, 2m x 4n, warp 32x64).
//   K-tiles of 128; adj staged via cp.async (latency hidden by MMA).
// ============================================================
#define KT 128
// smem (bytes): zs @0 ; A @1024 (16KB, single buf);
// B @17408 (2 x 64KB); adj @148480 (2 x 33792, 528B/row padded)
#define SM_ZS   0
#define SM_A    1024
#define SM_B    17408
#define SM_ADJ  148480
#define ADJ_BUF 33792
#define SMEM_ATTN 216064

__global__ void __launch_bounds__(256) k_attn(const int* __restrict__ adj,
                                              const float* __restrict__ bias,
                                              float* __restrict__ out) {
    extern __shared__ __align__(16) char smem[];
    const u32 sb = smem_u32(smem);
    const int tid  = threadIdx.x;
    const int lane = tid & 31;
    const int wid  = tid >> 5;
    const int wn   = wid & 3;          // n-warp: cols wn*64..+63
    const int wm   = wid >> 2;         // m-warp: rows wm*32..+31
    const int i0   = blockIdx.x * 64;

    // ---- A-producer role: thread -> (row ia, 32-j segment jq) ----
    const int ia = tid >> 2;           // 0..63
    const int jq = tid & 3;            // j offsets jq*32..+31
    const float s1v  = g_s1[i0 + ia];
    const float e1pv = g_e1p[i0 + ia];
    const float e1nv = g_e1n[i0 + ia];
    float zacc = 0.f;

    float acc[2][8][4];
    #pragma unroll
    for (int mi = 0; mi < 2; mi++)
        #pragma unroll
        for (int n8 = 0; n8 < 8; n8++)
            #pragma unroll
            for (int c = 0; c < 4; c++) acc[mi][n8][c] = 0.f;

    const int NTILE = NN / KT;   // 64

    // issue cp.async (B + adj) for tile tt into buffer bb
    #define ISSUE_TILE(tt, bb)                                                   \
    {                                                                            \
        const u32 dstB = sb + SM_B + (u32)(bb) * 65536u;                         \
        const size_t gof = (size_t)(tt) * 65536;                                 \
        _Pragma("unroll")                                                        \
        for (int it = 0; it < 16; it++) {                                        \
            u32 off = (u32)tid * 16u + (u32)it * 4096u;                          \
            cpa16(dstB + off, g_hh + gof + off);                                 \
        }                                                                        \
        const u32 dstA = sb + SM_ADJ + (u32)(bb) * (u32)ADJ_BUF;                 \
        _Pragma("unroll")                                                        \
        for (int it = 0; it < 8; it++) {                                         \
            u32 c = (u32)tid + (u32)it * 256u;                                   \
            u32 row = c >> 5, col = c & 31;                                      \
            cpa16(dstA + row * 528u + col * 16u,                                 \
                  adj + (size_t)(i0 + row) * NN + (size_t)(tt) * KT + col * 4);  \
        }                                                                        \
        cpa_commit();                                                            \
    }

    // ---- prologue: fetch tile 0 ----
    ISSUE_TILE(0, 0);

    // frag address pieces
    const u32 a_row_off = (u32)((wm * 32 + (lane & 15)) * 256);
    const u32 a_hi      = (u32)(lane >> 4);
    const u32 sxor      = (u32)(lane & 7);
    const u32 b_row_off = (u32)((lane & 15) * 512 + wn * 128);

    for (int t = 0; t < NTILE; t++) {
        const int buf = t & 1;
        cpa_wait0();        // tile t landed
        __syncthreads();    // visible to all; MMA(t-1) done -> A & buf^1 free

        if (t + 1 < NTILE) ISSUE_TILE(t + 1, buf ^ 1);

        // ---- pack P(t) from smem adj -> A (fp16, swizzled) ----
        {
            const int jbase = t * KT + jq * 32;
            const char* arow = smem + SM_ADJ + buf * ADJ_BUF + ia * 528 + jq * 128;
            char* Ah = smem + SM_A;
            u32 w[4];
            #pragma unroll
            for (int q = 0; q < 8; q++) {
                int4   av  = *(const int4*)(arow + q * 16);
                float4 s2q = *(const float4*)(g_s2  + jbase + q * 4);
                float4 p2q = *(const float4*)(g_e2p + jbase + q * 4);
                float4 n2q = *(const float4*)(g_e2n + jbase + q * 4);
                float p0 = (av.x > 0) ? ((s1v + s2q.x > 0.f) ? e1pv * p2q.x : e1nv * n2q.x) : 0.f;
                float p1 = (av.y > 0) ? ((s1v + s2q.y > 0.f) ? e1pv * p2q.y : e1nv * n2q.y) : 0.f;
                float p2 = (av.z > 0) ? ((s1v + s2q.z > 0.f) ? e1pv * p2q.z : e1nv * n2q.z) : 0.f;
                float p3 = (av.w > 0) ? ((s1v + s2q.w > 0.f) ? e1pv * p2q.w : e1nv * n2q.w) : 0.f;
                zacc += (p0 + p1) + (p2 + p3);
                int idx = (q & 1) * 2;
                w[idx]     = packh2(p0, p1);
                w[idx + 1] = packh2(p2, p3);
                if (q & 1) {
                    u32 chunk = (u32)(jq * 4 + (q >> 1));
                    u32 soff = (u32)ia * 256u + ((chunk ^ ((u32)ia & 7u)) << 4);
                    *(uint4*)(Ah + soff) = make_uint4(w[0], w[1], w[2], w[3]);
                }
            }
        }
        __syncthreads();    // A visible

        // ---- MMA(t) ----
        const u32 Abuf = sb + SM_A;
        const u32 Bbuf = sb + SM_B + (u32)buf * 65536u;
        #pragma unroll
        for (int kk = 0; kk < 8; kk++) {
            u32 afr[2][4];
            #pragma unroll
            for (int mi = 0; mi < 2; mi++) {
                u32 chunk = (u32)(kk * 2) + a_hi;
                ldsm4(afr[mi], Abuf + a_row_off + (u32)mi * 4096u
                                  + ((chunk ^ sxor) << 4));
            }
            u32 bfr[4][4];
            #pragma unroll
            for (int nb2 = 0; nb2 < 4; nb2++) {
                u32 chunk = (u32)(nb2 * 2) + a_hi;
                ldsm4t(bfr[nb2], Bbuf + (u32)(kk * 16) * 512u + b_row_off
                                    + ((chunk ^ sxor) << 4));
            }
            #pragma unroll
            for (int mi = 0; mi < 2; mi++)
                #pragma unroll
                for (int n8 = 0; n8 < 8; n8++)
                    mma16816(acc[mi][n8], afr[mi], &bfr[n8 >> 1][(n8 & 1) * 2]);
        }
    }

    // ---- Z reduce: 4 threads (adjacent lanes) per row ----
    zacc += __shfl_xor_sync(0xffffffffu, zacc, 1);
    zacc += __shfl_xor_sync(0xffffffffu, zacc, 2);
    float* zs = (float*)(smem + SM_ZS);
    __syncthreads();
    if ((tid & 3) == 0) zs[ia] = zacc;
    __syncthreads();

    // ---- epilogue: out = acc/Z + bias ----
    const int g  = lane >> 2;
    const int tq = lane & 3;
    #pragma unroll
    for (int mi = 0; mi < 2; mi++) {
        int rl0 = wm * 32 + mi * 16 + g;
        float z0 = zs[rl0], z8 = zs[rl0 + 8];
        float inv0 = (z0 > 0.f) ? 1.0f / z0 : 0.f;
        float inv8 = (z8 > 0.f) ? 1.0f / z8 : 0.f;
        float* o0 = out + (size_t)(i0 + rl0) * OUTF;
        float* o8 = out + (size_t)(i0 + rl0 + 8) * OUTF;
        #pragma unroll
        for (int n8 = 0; n8 < 8; n8++) {
            int col = wn * 64 + n8 * 8 + tq * 2;
            float2 b2 = *(const float2*)(bias + col);
            float2 r0, r8;
            r0.x = acc[mi][n8][0] * inv0 + b2.x;
            r0.y = acc[mi][n8][1] * inv0 + b2.y;
            r8.x = acc[mi][n8][2] * inv8 + b2.x;
            r8.y = acc[mi][n8][3] * inv8 + b2.y;
            *(float2*)(o0 + col) = r0;
            *(float2*)(o8 + col) = r8;
        }
    }
    #undef ISSUE_TILE
}

// ============================================================
extern "C" void kernel_launch(void* const* d_in, const int* in_sizes, int n_in,
                              void* d_out, int out_size) {
    (void)in_sizes; (void)n_in; (void)out_size;
    const float* x    = (const float*)d_in[0];
    const int*   adj  = (const int*)  d_in[1];
    const float* W    = (const float*)d_in[2];
    const float* a    = (const float*)d_in[3];
    const float* bias = (const float*)d_in[4];
    float* out = (float*)d_out;

    cudaFuncSetAttribute(k_attn, cudaFuncAttributeMaxDynamicSharedMemorySize, SMEM_ATTN);

    k_xw  <<<NN / 32, 256>>>(x, W);
    k_s   <<<NN / 8, 256>>>(a);
    k_attn<<<NN / 64, 256, SMEM_ATTN>>>(adj, bias, out);
}

// round 7
// speedup vs baseline: 3.9608x; 1.2323x over previous
#include <cuda_runtime.h>
#include <cuda_bf16.h>
#include <cuda_fp16.h>
#include <cstdint>
#include <cstddef>

#define NN    8192
#define INF_  512
#define OUTF  256
#define ALPHA 0.2f

typedef unsigned long long u64;
typedef unsigned int u32;

// ---------------- scratch globals (no allocs allowed) ----------------
__device__ float g_h[NN * OUTF];
__device__ float g_s1[NN];
__device__ float g_s2[NN];
__device__ float g_e1p[NN];   // exp(s1)
__device__ float g_e1n[NN];   // exp(ALPHA*s1)
__device__ float g_e2p[NN];   // exp(s2)
__device__ float g_e2n[NN];   // exp(ALPHA*s2)
// h as fp16, PRE-SWIZZLED in the attention B-tile layout:
// byte(j, n) = j*512 + (((n>>3) ^ (j&7))<<4) + (n&7)*2
__device__ __align__(16) unsigned char g_hh[(size_t)NN * 512];

// ---------------- packed fp32x2 helpers (k_xw) ----------------
__device__ __forceinline__ u64 pk2(float x, float y) {
    u64 r; asm("mov.b64 %0, {%1, %2};" : "=l"(r) : "f"(x), "f"(y)); return r;
}
__device__ __forceinline__ void upk2(u64 v, float &x, float &y) {
    asm("mov.b64 {%0, %1}, %2;" : "=f"(x), "=f"(y) : "l"(v));
}
__device__ __forceinline__ void fma2(u64 &d, u64 a, u64 b) {
    asm("fma.rn.f32x2 %0, %1, %2, %3;" : "=l"(d) : "l"(a), "l"(b), "l"(d));
}

// ---------------- mma / ldmatrix / cp.async / barrier helpers ----------------
__device__ __forceinline__ u32 smem_u32(const void* p) {
    u32 a;
    asm("{ .reg .u64 t; cvta.to.shared.u64 t, %1; cvt.u32.u64 %0, t; }"
        : "=r"(a) : "l"(p));
    return a;
}
__device__ __forceinline__ void ldsm4(u32* r, u32 addr) {
    asm volatile("ldmatrix.sync.aligned.m8n8.x4.shared.b16 {%0,%1,%2,%3}, [%4];"
                 : "=r"(r[0]), "=r"(r[1]), "=r"(r[2]), "=r"(r[3]) : "r"(addr));
}
__device__ __forceinline__ void ldsm4t(u32* r, u32 addr) {
    asm volatile("ldmatrix.sync.aligned.m8n8.x4.trans.shared.b16 {%0,%1,%2,%3}, [%4];"
                 : "=r"(r[0]), "=r"(r[1]), "=r"(r[2]), "=r"(r[3]) : "r"(addr));
}
__device__ __forceinline__ void mma16816(float* d, const u32* a, const u32* b) {
    asm volatile(
        "mma.sync.aligned.m16n8k16.row.col.f32.f16.f16.f32 "
        "{%0,%1,%2,%3}, {%4,%5,%6,%7}, {%8,%9}, {%0,%1,%2,%3};"
        : "+f"(d[0]), "+f"(d[1]), "+f"(d[2]), "+f"(d[3])
        : "r"(a[0]), "r"(a[1]), "r"(a[2]), "r"(a[3]), "r"(b[0]), "r"(b[1]));
}
__device__ __forceinline__ void cpa16(u32 dst, const void* src) {
    asm volatile("cp.async.cg.shared.global [%0], [%1], 16;"
                 :: "r"(dst), "l"(src) : "memory");
}
__device__ __forceinline__ void cpa_commit() {
    asm volatile("cp.async.commit_group;" ::: "memory");
}
__device__ __forceinline__ void cpa_wait0() {
    asm volatile("cp.async.wait_group 0;" ::: "memory");
}
__device__ __forceinline__ u32 packh2(float a, float b) {
    __half2 h = __floats2half2_rn(a, b);
    return *reinterpret_cast<u32*>(&h);
}
__device__ __forceinline__ void bar_sync(int id, int cnt) {
    asm volatile("bar.sync %0, %1;" :: "r"(id), "r"(cnt) : "memory");
}
__device__ __forceinline__ void bar_arrive(int id, int cnt) {
    asm volatile("bar.arrive %0, %1;" :: "r"(id), "r"(cnt) : "memory");
}

// ============================================================
// Kernel 1: h = x @ W ; also emits fp16 pre-swizzled copy
//   grid 128 (single wave), 512 threads, 64 rows/CTA, tile 8r x 4c
// ============================================================
__global__ void __launch_bounds__(512) k_xw(const float* __restrict__ x,
                                            const float* __restrict__ W) {
    __shared__ __align__(16) float xs[32][68];
    __shared__ __align__(16) float ws[32][256];

    const int tid = threadIdx.x;
    const int i0  = blockIdx.x * 64;
    const int ty  = tid >> 6;       // 0..7 -> rows ty*8 .. +7
    const int tx  = tid & 63;       // cols tx*4 .. +3

    u64 acc[4][4];
    #pragma unroll
    for (int r = 0; r < 4; r++)
        #pragma unroll
        for (int c = 0; c < 4; c++) acc[r][c] = 0ull;

    for (int k0 = 0; k0 < INF_; k0 += 32) {
        __syncthreads();
        #pragma unroll
        for (int i = 0; i < 4; i++) {
            int idx = tid + i * 512;
            int kk = idx & 31, r = idx >> 5;
            xs[kk][r] = x[(size_t)(i0 + r) * INF_ + k0 + kk];
        }
        #pragma unroll
        for (int i = 0; i < 4; i++) {
            int f4 = tid + i * 512;
            int kk = f4 >> 6; int c4 = (f4 & 63) << 2;
            *(float4*)&ws[kk][c4] = *(const float4*)&W[(size_t)(k0 + kk) * OUTF + c4];
        }
        __syncthreads();

        #pragma unroll 8
        for (int kk = 0; kk < 32; kk++) {
            const ulonglong2* xr = (const ulonglong2*)&xs[kk][ty * 8];
            ulonglong2 q0 = xr[0], q1 = xr[1];
            u64 xp[4] = {q0.x, q0.y, q1.x, q1.y};
            float4 wv = *(const float4*)&ws[kk][tx * 4];
            u64 w0 = pk2(wv.x, wv.x), w1 = pk2(wv.y, wv.y);
            u64 w2 = pk2(wv.z, wv.z), w3 = pk2(wv.w, wv.w);
            #pragma unroll
            for (int r = 0; r < 4; r++) {
                fma2(acc[r][0], xp[r], w0);
                fma2(acc[r][1], xp[r], w1);
                fma2(acc[r][2], xp[r], w2);
                fma2(acc[r][3], xp[r], w3);
            }
        }
    }

    #pragma unroll
    for (int rp = 0; rp < 4; rp++) {
        int row_lo = ty * 8 + 2 * rp;
        float lx[4], hx[4];
        #pragma unroll
        for (int c = 0; c < 4; c++) upk2(acc[rp][c], lx[c], hx[c]);
        #pragma unroll
        for (int half = 0; half < 2; half++) {
            int j = i0 + row_lo + half;
            float* v = half ? hx : lx;
            float4 o; o.x = v[0]; o.y = v[1]; o.z = v[2]; o.w = v[3];
            *(float4*)&g_h[(size_t)j * OUTF + tx * 4] = o;
            u32 h01 = packh2(v[0], v[1]);
            u32 h23 = packh2(v[2], v[3]);
            u32 off = (u32)j * 512u + ((((u32)(tx >> 1)) ^ ((u32)j & 7u)) << 4)
                    + ((u32)(tx & 1)) * 8u;
            *(u64*)(g_hh + off) = (u64)h01 | ((u64)h23 << 32);
        }
    }
}

// ============================================================
// Kernel 2: s1/s2 + factorized exp tables
// ============================================================
__global__ void __launch_bounds__(256) k_s(const float* __restrict__ a) {
    int row  = blockIdx.x * 8 + (threadIdx.x >> 5);
    int lane = threadIdx.x & 31;
    const float* hr = g_h + (size_t)row * OUTF;
    float p1 = 0.f, p2 = 0.f;
    #pragma unroll
    for (int c = lane; c < OUTF; c += 32) {
        float hv = hr[c];
        p1 += hv * a[c];
        p2 += hv * a[OUTF + c];
    }
    #pragma unroll
    for (int off = 16; off; off >>= 1) {
        p1 += __shfl_xor_sync(0xffffffffu, p1, off);
        p2 += __shfl_xor_sync(0xffffffffu, p2, off);
    }
    if (lane == 0) {
        g_s1[row]  = p1;
        g_s2[row]  = p2;
        g_e1p[row] = __expf(p1);
        g_e1n[row] = __expf(ALPHA * p1);
        g_e2p[row] = __expf(p2);
        g_e2n[row] = __expf(ALPHA * p2);
    }
}

// ============================================================
// Kernel 3: warp-specialized fused masked-softmax + P@h
//   384 threads: warps 0-7 = MMA consumers (M=64 x N=256, warp 32x64)
//                warps 8-11 = producers (adj LDG + pack + B cp.async)
//   KT=128, double-buffered A (16KB x2) + B (64KB x2),
//   named-barrier full/empty handshakes.
// ============================================================
#define KT 128
#define NTILE (NN / KT)
// smem: zpart[2][64] floats @0 ; A @1024 (2 x 16KB); B @33792 (2 x 64KB)
#define SM_ZP   0
#define SM_A    1024
#define SM_B    33792
#define SMEM_ATTN 164864
// named barriers: full[p] = 1+p, empty[p] = 3+p, all count=384
#define NTHREADS 384

__global__ void __launch_bounds__(NTHREADS) k_attn(const int* __restrict__ adj,
                                                   const float* __restrict__ bias,
                                                   float* __restrict__ out) {
    extern __shared__ __align__(16) char smem[];
    const u32 sb = smem_u32(smem);
    const int tid  = threadIdx.x;
    const int lane = tid & 31;
    const int wid  = tid >> 5;
    const int i0   = blockIdx.x * 64;
    float* zp = (float*)(smem + SM_ZP);    // zpart[2][64]

    if (wid < 8) {
        // ================= CONSUMERS: MMA =================
        const int wn = wid & 3;          // cols wn*64..+63
        const int wm = wid >> 2;         // rows wm*32..+31

        float acc[2][8][4];
        #pragma unroll
        for (int mi = 0; mi < 2; mi++)
            #pragma unroll
            for (int n8 = 0; n8 < 8; n8++)
                #pragma unroll
                for (int c = 0; c < 4; c++) acc[mi][n8][c] = 0.f;

        const u32 a_row_off = (u32)((wm * 32 + (lane & 15)) * 256);
        const u32 a_hi      = (u32)(lane >> 4);
        const u32 sxor      = (u32)(lane & 7);
        const u32 b_row_off = (u32)((lane & 15) * 512 + wn * 128);

        for (int t = 0; t < NTILE; t++) {
            const int p = t & 1;
            bar_sync(1 + p, NTHREADS);   // wait full[p]

            const u32 Abuf = sb + SM_A + (u32)p * 16384u;
            const u32 Bbuf = sb + SM_B + (u32)p * 65536u;
            #pragma unroll
            for (int kk = 0; kk < 8; kk++) {
                u32 afr[2][4];
                #pragma unroll
                for (int mi = 0; mi < 2; mi++) {
                    u32 chunk = (u32)(kk * 2) + a_hi;
                    ldsm4(afr[mi], Abuf + a_row_off + (u32)mi * 4096u
                                      + ((chunk ^ sxor) << 4));
                }
                u32 bfr[4][4];
                #pragma unroll
                for (int nb2 = 0; nb2 < 4; nb2++) {
                    u32 chunk = (u32)(nb2 * 2) + a_hi;
                    ldsm4t(bfr[nb2], Bbuf + (u32)(kk * 16) * 512u + b_row_off
                                        + ((chunk ^ sxor) << 4));
                }
                #pragma unroll
                for (int mi = 0; mi < 2; mi++)
                    #pragma unroll
                    for (int n8 = 0; n8 < 8; n8++)
                        mma16816(acc[mi][n8], afr[mi], &bfr[n8 >> 1][(n8 & 1) * 2]);
            }
            bar_arrive(3 + p, NTHREADS); // signal empty[p]
        }

        __syncthreads();   // producers have written zp

        // ---- epilogue: out = acc/Z + bias ----
        const int g  = lane >> 2;
        const int tq = lane & 3;
        #pragma unroll
        for (int mi = 0; mi < 2; mi++) {
            int rl0 = wm * 32 + mi * 16 + g;
            float z0 = zp[rl0]     + zp[64 + rl0];
            float z8 = zp[rl0 + 8] + zp[64 + rl0 + 8];
            float inv0 = (z0 > 0.f) ? 1.0f / z0 : 0.f;
            float inv8 = (z8 > 0.f) ? 1.0f / z8 : 0.f;
            float* o0 = out + (size_t)(i0 + rl0) * OUTF;
            float* o8 = out + (size_t)(i0 + rl0 + 8) * OUTF;
            #pragma unroll
            for (int n8 = 0; n8 < 8; n8++) {
                int col = wn * 64 + n8 * 8 + tq * 2;
                float2 b2 = *(const float2*)(bias + col);
                float2 r0, r8;
                r0.x = acc[mi][n8][0] * inv0 + b2.x;
                r0.y = acc[mi][n8][1] * inv0 + b2.y;
                r8.x = acc[mi][n8][2] * inv8 + b2.x;
                r8.y = acc[mi][n8][3] * inv8 + b2.y;
                *(float2*)(o0 + col) = r0;
                *(float2*)(o8 + col) = r8;
            }
        }
    } else {
        // ================= PRODUCERS: fetch + pack =================
        const int ptid = tid - 256;        // 0..127
        const int ia   = ptid & 63;        // row within tile
        const int hseg = ptid >> 6;        // 0/1 -> j half (64 each)
        const float s1v  = g_s1[i0 + ia];
        const float e1pv = g_e1p[i0 + ia];
        const float e1nv = g_e1n[i0 + ia];
        float zacc = 0.f;

        for (int tp = 0; tp < NTILE; tp++) {
            const int p = tp & 1;
            if (tp >= 2) bar_sync(3 + p, NTHREADS);   // wait empty[p]

            // ---- issue B cp.async (64KB, pre-swizzled fp16 h) ----
            {
                const u32 dstB = sb + SM_B + (u32)p * 65536u;
                const unsigned char* src = g_hh + (size_t)tp * 65536 + ptid * 16;
                #pragma unroll
                for (int it = 0; it < 32; it++)
                    cpa16(dstB + (u32)ptid * 16u + (u32)it * 2048u, src + it * 2048);
                cpa_commit();
            }

            // ---- pack P tile (64 x 128 fp16, swizzled) into A[p] ----
            {
                const int jbase = tp * KT + hseg * 64;
                const int* arow = adj + (size_t)(i0 + ia) * NN + jbase;
                char* Ah = smem + SM_A + p * 16384;
                u32 w[4];
                #pragma unroll
                for (int q = 0; q < 16; q++) {
                    int4   av  = *(const int4*)(arow + q * 4);
                    float4 s2q = *(const float4*)(g_s2  + jbase + q * 4);
                    float4 p2q = *(const float4*)(g_e2p + jbase + q * 4);
                    float4 n2q = *(const float4*)(g_e2n + jbase + q * 4);
                    float p0 = (av.x > 0) ? ((s1v + s2q.x > 0.f) ? e1pv * p2q.x : e1nv * n2q.x) : 0.f;
                    float p1 = (av.y > 0) ? ((s1v + s2q.y > 0.f) ? e1pv * p2q.y : e1nv * n2q.y) : 0.f;
                    float p2 = (av.z > 0) ? ((s1v + s2q.z > 0.f) ? e1pv * p2q.z : e1nv * n2q.z) : 0.f;
                    float p3 = (av.w > 0) ? ((s1v + s2q.w > 0.f) ? e1pv * p2q.w : e1nv * n2q.w) : 0.f;
                    zacc += (p0 + p1) + (p2 + p3);
                    int idx = (q & 1) * 2;
                    w[idx]     = packh2(p0, p1);
                    w[idx + 1] = packh2(p2, p3);
                    if (q & 1) {
                        u32 chunk = (u32)(hseg * 8 + (q >> 1));
                        u32 soff = (u32)ia * 256u + ((chunk ^ ((u32)ia & 7u)) << 4);
                        *(uint4*)(Ah + soff) = make_uint4(w[0], w[1], w[2], w[3]);
                    }
                }
            }

            cpa_wait0();                  // B[p] landed
            bar_arrive(1 + p, NTHREADS);  // signal full[p]
        }

        // Z partials
        zp[hseg * 64 + ia] = zacc;
        __syncthreads();
    }
}

// ============================================================
extern "C" void kernel_launch(void* const* d_in, const int* in_sizes, int n_in,
                              void* d_out, int out_size) {
    (void)in_sizes; (void)n_in; (void)out_size;
    const float* x    = (const float*)d_in[0];
    const int*   adj  = (const int*)  d_in[1];
    const float* W    = (const float*)d_in[2];
    const float* a    = (const float*)d_in[3];
    const float* bias = (const float*)d_in[4];
    float* out = (float*)d_out;

    cudaFuncSetAttribute(k_attn, cudaFuncAttributeMaxDynamicSharedMemorySize, SMEM_ATTN);

    k_xw  <<<NN / 64, 512>>>(x, W);
    k_s   <<<NN / 8, 256>>>(a);
    k_attn<<<NN / 64, NTHREADS, SMEM_ATTN>>>(adj, bias, out);
}

// round 8
// speedup vs baseline: 6.0477x; 1.5269x over previous
#include <cuda_runtime.h>
#include <cuda_fp16.h>
#include <cstdint>
#include <cstddef>

#define NN    8192
#define INF_  512
#define OUTF  256
#define ALPHA 0.2f

typedef unsigned long long u64;
typedef unsigned int u32;

// ---------------- scratch globals (no allocs allowed) ----------------
__device__ float g_h[NN * OUTF];
__device__ float g_s1[NN];
__device__ float g_s2[NN];
__device__ float g_e1p[NN];   // exp(s1)
__device__ float g_e1n[NN];   // exp(ALPHA*s1)
__device__ float g_e2p[NN];   // exp(s2)
__device__ float g_e2n[NN];   // exp(ALPHA*s2)
// h as fp16, PRE-SWIZZLED B-layout: byte(j,n) = j*512 + (((n>>3)^(j&7))<<4) + (n&7)*2
__device__ __align__(16) unsigned char g_hh[(size_t)NN * 512];
// x as fp16, PRE-SWIZZLED A-layout per 128-k tile:
// byte = ktile*2MB + i*256 + (((kc)^(i&7))<<4) + (k&7)*2,  kc = (k%128)/8
__device__ __align__(16) unsigned char g_xh[(size_t)NN * 1024];
// W as fp16, PRE-SWIZZLED B-layout per 128-k tile:
// byte = ktile*64KB + kl*512 + (((n>>3)^(kl&7))<<4) + (n&7)*2
__device__ __align__(16) unsigned char g_wh[(size_t)INF_ * 512];

// ---------------- mma / ldmatrix / cp.async / barrier helpers ----------------
__device__ __forceinline__ u32 smem_u32(const void* p) {
    u32 a;
    asm("{ .reg .u64 t; cvta.to.shared.u64 t, %1; cvt.u32.u64 %0, t; }"
        : "=r"(a) : "l"(p));
    return a;
}
__device__ __forceinline__ void ldsm4(u32* r, u32 addr) {
    asm volatile("ldmatrix.sync.aligned.m8n8.x4.shared.b16 {%0,%1,%2,%3}, [%4];"
                 : "=r"(r[0]), "=r"(r[1]), "=r"(r[2]), "=r"(r[3]) : "r"(addr));
}
__device__ __forceinline__ void ldsm4t(u32* r, u32 addr) {
    asm volatile("ldmatrix.sync.aligned.m8n8.x4.trans.shared.b16 {%0,%1,%2,%3}, [%4];"
                 : "=r"(r[0]), "=r"(r[1]), "=r"(r[2]), "=r"(r[3]) : "r"(addr));
}
__device__ __forceinline__ void mma16816(float* d, const u32* a, const u32* b) {
    asm volatile(
        "mma.sync.aligned.m16n8k16.row.col.f32.f16.f16.f32 "
        "{%0,%1,%2,%3}, {%4,%5,%6,%7}, {%8,%9}, {%0,%1,%2,%3};"
        : "+f"(d[0]), "+f"(d[1]), "+f"(d[2]), "+f"(d[3])
        : "r"(a[0]), "r"(a[1]), "r"(a[2]), "r"(a[3]), "r"(b[0]), "r"(b[1]));
}
__device__ __forceinline__ void cpa16(u32 dst, const void* src) {
    asm volatile("cp.async.cg.shared.global [%0], [%1], 16;"
                 :: "r"(dst), "l"(src) : "memory");
}
__device__ __forceinline__ void cpa_commit() {
    asm volatile("cp.async.commit_group;" ::: "memory");
}
__device__ __forceinline__ void cpa_wait0() {
    asm volatile("cp.async.wait_group 0;" ::: "memory");
}
__device__ __forceinline__ void cpa_wait1() {
    asm volatile("cp.async.wait_group 1;" ::: "memory");
}
__device__ __forceinline__ u32 packh2(float a, float b) {
    __half2 h = __floats2half2_rn(a, b);
    return *reinterpret_cast<u32*>(&h);
}
__device__ __forceinline__ void bar_sync(int id, int cnt) {
    asm volatile("bar.sync %0, %1;" :: "r"(id), "r"(cnt) : "memory");
}
__device__ __forceinline__ void bar_arrive(int id, int cnt) {
    asm volatile("bar.arrive %0, %1;" :: "r"(id), "r"(cnt) : "memory");
}

// ============================================================
// Kernel 0: convert x -> g_xh (A-layout) and W -> g_wh (B-layout)
// ============================================================
__global__ void __launch_bounds__(256) k_cvt(const float* __restrict__ x,
                                             const float* __restrict__ W) {
    int gid = blockIdx.x * 256 + threadIdx.x;     // 524288 total
    {
        int i = gid >> 6;            // row 0..8191
        int c = gid & 63;            // 8-elem chunk within row (k = c*8)
        int ktile = c >> 4;
        int kc = c & 15;
        const float4* src = (const float4*)(x + (size_t)i * INF_ + c * 8);
        float4 a = src[0], b = src[1];
        uint4 o = make_uint4(packh2(a.x, a.y), packh2(a.z, a.w),
                             packh2(b.x, b.y), packh2(b.z, b.w));
        u32 off = (u32)ktile * 2097152u + (u32)i * 256u
                + ((((u32)kc) ^ ((u32)i & 7u)) << 4);
        *(uint4*)(g_xh + off) = o;
    }
    if (gid < 16384) {
        int k = gid >> 5;            // 0..511
        int c = gid & 31;            // n-chunk (n = c*8)
        int ktile = k >> 7, kl = k & 127;
        const float4* src = (const float4*)(W + (size_t)k * OUTF + c * 8);
        float4 a = src[0], b = src[1];
        uint4 o = make_uint4(packh2(a.x, a.y), packh2(a.z, a.w),
                             packh2(b.x, b.y), packh2(b.z, b.w));
        u32 off = (u32)ktile * 65536u + (u32)kl * 512u
                + ((((u32)c) ^ ((u32)kl & 7u)) << 4);
        *(uint4*)(g_wh + off) = o;
    }
}

// ============================================================
// Kernel 1: h = x @ W via fp16 mma.sync; writes g_h (fp32) + g_hh (fp16 swz)
//   grid 128, 256 threads (8 warps 2m x 4n, warp 32x64), 4 k-tiles of 128.
// ============================================================
#define XW_SMA 0
#define XW_SMB 32768
#define XW_SMEM 163840

__global__ void __launch_bounds__(256) k_xw_mma() {
    extern __shared__ __align__(16) char smem[];
    const u32 sb = smem_u32(smem);
    const int tid  = threadIdx.x;
    const int lane = tid & 31;
    const int wid  = tid >> 5;
    const int wn   = wid & 3;
    const int wm   = wid >> 2;
    const int i0   = blockIdx.x * 64;

    float acc[2][8][4];
    #pragma unroll
    for (int mi = 0; mi < 2; mi++)
        #pragma unroll
        for (int n8 = 0; n8 < 8; n8++)
            #pragma unroll
            for (int c = 0; c < 4; c++) acc[mi][n8][c] = 0.f;

    #define XW_ISSUE(kt, bb)                                                     \
    {                                                                            \
        const u32 dstA = sb + XW_SMA + (u32)(bb) * 16384u;                       \
        const unsigned char* srcA = g_xh + (size_t)(kt) * 2097152 + (size_t)i0 * 256; \
        _Pragma("unroll")                                                        \
        for (int it = 0; it < 4; it++) {                                         \
            u32 off = (u32)tid * 16u + (u32)it * 4096u;                          \
            cpa16(dstA + off, srcA + off);                                       \
        }                                                                        \
        const u32 dstB = sb + XW_SMB + (u32)(bb) * 65536u;                       \
        const unsigned char* srcB = g_wh + (size_t)(kt) * 65536;                 \
        _Pragma("unroll")                                                        \
        for (int it = 0; it < 16; it++) {                                        \
            u32 off = (u32)tid * 16u + (u32)it * 4096u;                          \
            cpa16(dstB + off, srcB + off);                                       \
        }                                                                        \
        cpa_commit();                                                            \
    }

    XW_ISSUE(0, 0);

    const u32 a_row_off = (u32)((wm * 32 + (lane & 15)) * 256);
    const u32 a_hi      = (u32)(lane >> 4);
    const u32 sxor      = (u32)(lane & 7);
    const u32 b_row_off = (u32)((lane & 15) * 512 + wn * 128);

    for (int kt = 0; kt < 4; kt++) {
        const int buf = kt & 1;
        if (kt < 3) { XW_ISSUE(kt + 1, buf ^ 1); cpa_wait1(); }
        else        { cpa_wait0(); }
        __syncthreads();

        const u32 Abuf = sb + XW_SMA + (u32)buf * 16384u;
        const u32 Bbuf = sb + XW_SMB + (u32)buf * 65536u;
        #pragma unroll
        for (int kk = 0; kk < 8; kk++) {
            u32 afr[2][4];
            #pragma unroll
            for (int mi = 0; mi < 2; mi++) {
                u32 chunk = (u32)(kk * 2) + a_hi;
                ldsm4(afr[mi], Abuf + a_row_off + (u32)mi * 4096u
                                  + ((chunk ^ sxor) << 4));
            }
            u32 bfr[4][4];
            #pragma unroll
            for (int nb2 = 0; nb2 < 4; nb2++) {
                u32 chunk = (u32)(nb2 * 2) + a_hi;
                ldsm4t(bfr[nb2], Bbuf + (u32)(kk * 16) * 512u + b_row_off
                                    + ((chunk ^ sxor) << 4));
            }
            #pragma unroll
            for (int mi = 0; mi < 2; mi++)
                #pragma unroll
                for (int n8 = 0; n8 < 8; n8++)
                    mma16816(acc[mi][n8], afr[mi], &bfr[n8 >> 1][(n8 & 1) * 2]);
        }
        __syncthreads();
    }

    // epilogue: write g_h fp32 + g_hh fp16 swizzled
    const int g  = lane >> 2;
    const int tq = lane & 3;
    #pragma unroll
    for (int mi = 0; mi < 2; mi++) {
        int rl0 = wm * 32 + mi * 16 + g;
        int j0r = i0 + rl0, j8r = i0 + rl0 + 8;
        #pragma unroll
        for (int n8 = 0; n8 < 8; n8++) {
            int col = wn * 64 + n8 * 8 + tq * 2;
            float2 h0 = make_float2(acc[mi][n8][0], acc[mi][n8][1]);
            float2 h8 = make_float2(acc[mi][n8][2], acc[mi][n8][3]);
            *(float2*)&g_h[(size_t)j0r * OUTF + col] = h0;
            *(float2*)&g_h[(size_t)j8r * OUTF + col] = h8;
            u32 off0 = (u32)j0r * 512u + ((((u32)(col >> 3)) ^ ((u32)j0r & 7u)) << 4)
                     + ((u32)(col & 7)) * 2u;
            u32 off8 = (u32)j8r * 512u + ((((u32)(col >> 3)) ^ ((u32)j8r & 7u)) << 4)
                     + ((u32)(col & 7)) * 2u;
            *(u32*)(g_hh + off0) = packh2(h0.x, h0.y);
            *(u32*)(g_hh + off8) = packh2(h8.x, h8.y);
        }
    }
    #undef XW_ISSUE
}

// ============================================================
// Kernel 2: s1/s2 + factorized exp tables
// ============================================================
__global__ void __launch_bounds__(256) k_s(const float* __restrict__ a) {
    int row  = blockIdx.x * 8 + (threadIdx.x >> 5);
    int lane = threadIdx.x & 31;
    const float* hr = g_h + (size_t)row * OUTF;
    float p1 = 0.f, p2 = 0.f;
    #pragma unroll
    for (int c = lane; c < OUTF; c += 32) {
        float hv = hr[c];
        p1 += hv * a[c];
        p2 += hv * a[OUTF + c];
    }
    #pragma unroll
    for (int off = 16; off; off >>= 1) {
        p1 += __shfl_xor_sync(0xffffffffu, p1, off);
        p2 += __shfl_xor_sync(0xffffffffu, p2, off);
    }
    if (lane == 0) {
        g_s1[row]  = p1;
        g_s2[row]  = p2;
        g_e1p[row] = __expf(p1);
        g_e1n[row] = __expf(ALPHA * p1);
        g_e2p[row] = __expf(p2);
        g_e2n[row] = __expf(ALPHA * p2);
    }
}

// ============================================================
// Kernel 3: warp-specialized fused masked-softmax + P@h
//   512 threads: warps 0-7 consumers (MMA), warps 8-15 producers.
// ============================================================
#define KT 128
#define NTILE (NN / KT)
#define SM_ZP   0
#define SM_A    1024
#define SM_B    33792
#define SMEM_ATTN 164864
#define NTHREADS 512

__global__ void __launch_bounds__(NTHREADS) k_attn(const int* __restrict__ adj,
                                                   const float* __restrict__ bias,
                                                   float* __restrict__ out) {
    extern __shared__ __align__(16) char smem[];
    const u32 sb = smem_u32(smem);
    const int tid  = threadIdx.x;
    const int lane = tid & 31;
    const int wid  = tid >> 5;
    const int i0   = blockIdx.x * 64;
    float* zp = (float*)(smem + SM_ZP);    // zpart[4][64]

    if (wid < 8) {
        // ================= CONSUMERS: MMA =================
        const int wn = wid & 3;
        const int wm = wid >> 2;

        float acc[2][8][4];
        #pragma unroll
        for (int mi = 0; mi < 2; mi++)
            #pragma unroll
            for (int n8 = 0; n8 < 8; n8++)
                #pragma unroll
                for (int c = 0; c < 4; c++) acc[mi][n8][c] = 0.f;

        const u32 a_row_off = (u32)((wm * 32 + (lane & 15)) * 256);
        const u32 a_hi      = (u32)(lane >> 4);
        const u32 sxor      = (u32)(lane & 7);
        const u32 b_row_off = (u32)((lane & 15) * 512 + wn * 128);

        for (int t = 0; t < NTILE; t++) {
            const int p = t & 1;
            bar_sync(1 + p, NTHREADS);   // wait full[p]

            const u32 Abuf = sb + SM_A + (u32)p * 16384u;
            const u32 Bbuf = sb + SM_B + (u32)p * 65536u;
            #pragma unroll
            for (int kk = 0; kk < 8; kk++) {
                u32 afr[2][4];
                #pragma unroll
                for (int mi = 0; mi < 2; mi++) {
                    u32 chunk = (u32)(kk * 2) + a_hi;
                    ldsm4(afr[mi], Abuf + a_row_off + (u32)mi * 4096u
                                      + ((chunk ^ sxor) << 4));
                }
                u32 bfr[4][4];
                #pragma unroll
                for (int nb2 = 0; nb2 < 4; nb2++) {
                    u32 chunk = (u32)(nb2 * 2) + a_hi;
                    ldsm4t(bfr[nb2], Bbuf + (u32)(kk * 16) * 512u + b_row_off
                                        + ((chunk ^ sxor) << 4));
                }
                #pragma unroll
                for (int mi = 0; mi < 2; mi++)
                    #pragma unroll
                    for (int n8 = 0; n8 < 8; n8++)
                        mma16816(acc[mi][n8], afr[mi], &bfr[n8 >> 1][(n8 & 1) * 2]);
            }
            bar_arrive(3 + p, NTHREADS); // signal empty[p]
        }

        __syncthreads();   // producers have written zp

        // ---- epilogue: out = acc/Z + bias ----
        const int g  = lane >> 2;
        const int tq = lane & 3;
        #pragma unroll
        for (int mi = 0; mi < 2; mi++) {
            int rl0 = wm * 32 + mi * 16 + g;
            float z0 = (zp[rl0]       + zp[64 + rl0])
                     + (zp[128 + rl0] + zp[192 + rl0]);
            float z8 = (zp[rl0 + 8]       + zp[64 + rl0 + 8])
                     + (zp[128 + rl0 + 8] + zp[192 + rl0 + 8]);
            float inv0 = (z0 > 0.f) ? 1.0f / z0 : 0.f;
            float inv8 = (z8 > 0.f) ? 1.0f / z8 : 0.f;
            float* o0 = out + (size_t)(i0 + rl0) * OUTF;
            float* o8 = out + (size_t)(i0 + rl0 + 8) * OUTF;
            #pragma unroll
            for (int n8 = 0; n8 < 8; n8++) {
                int col = wn * 64 + n8 * 8 + tq * 2;
                float2 b2 = *(const float2*)(bias + col);
                float2 r0, r8;
                r0.x = acc[mi][n8][0] * inv0 + b2.x;
                r0.y = acc[mi][n8][1] * inv0 + b2.y;
                r8.x = acc[mi][n8][2] * inv8 + b2.x;
                r8.y = acc[mi][n8][3] * inv8 + b2.y;
                *(float2*)(o0 + col) = r0;
                *(float2*)(o8 + col) = r8;
            }
        }
    } else {
        // ================= PRODUCERS: fetch + pack =================
        const int ptid = tid - 256;        // 0..255
        const int ia   = ptid >> 2;        // row 0..63
        const int s    = ptid & 3;         // j interleave slot
        const float s1v  = g_s1[i0 + ia];
        const float e1pv = g_e1p[i0 + ia];
        const float e1nv = g_e1n[i0 + ia];
        float zacc = 0.f;

        const int* arowg = adj + (size_t)(i0 + ia) * NN + s * 4;

        for (int tp = 0; tp < NTILE; tp++) {
            const int p = tp & 1;
            if (tp >= 2) bar_sync(3 + p, NTHREADS);   // wait empty[p]

            // ---- issue B cp.async (64KB pre-swizzled fp16 h) ----
            {
                const u32 dstB = sb + SM_B + (u32)p * 65536u;
                const unsigned char* src = g_hh + (size_t)tp * 65536 + ptid * 16;
                #pragma unroll
                for (int it = 0; it < 16; it++)
                    cpa16(dstB + (u32)ptid * 16u + (u32)it * 4096u, src + it * 4096);
                cpa_commit();
            }

            // ---- pack P tile (64x128 fp16, swizzled) into A[p] ----
            // thread covers j = tp*KT + q*16 + s*4 .. +3, q=0..7 (coalesced int4)
            {
                const int jb0 = tp * KT + s * 4;
                const int* arow = arowg + tp * KT;
                char* Ah = smem + SM_A + p * 16384;
                #pragma unroll
                for (int q = 0; q < 8; q++) {
                    int jb = jb0 + q * 16;
                    int4   av  = *(const int4*)(arow + q * 16);
                    float4 s2q = *(const float4*)(g_s2  + jb);
                    float4 p2q = *(const float4*)(g_e2p + jb);
                    float4 n2q = *(const float4*)(g_e2n + jb);
                    float p0 = (av.x > 0) ? ((s1v + s2q.x > 0.f) ? e1pv * p2q.x : e1nv * n2q.x) : 0.f;
                    float p1 = (av.y > 0) ? ((s1v + s2q.y > 0.f) ? e1pv * p2q.y : e1nv * n2q.y) : 0.f;
                    float p2 = (av.z > 0) ? ((s1v + s2q.z > 0.f) ? e1pv * p2q.z : e1nv * n2q.z) : 0.f;
                    float p3 = (av.w > 0) ? ((s1v + s2q.w > 0.f) ? e1pv * p2q.w : e1nv * n2q.w) : 0.f;
                    zacc += (p0 + p1) + (p2 + p3);
                    u32 lo = packh2(p0, p1), hi = packh2(p2, p3);
                    u32 chunk = (u32)(q * 2 + (s >> 1));
                    u32 soff = (u32)ia * 256u + ((chunk ^ ((u32)ia & 7u)) << 4)
                             + (u32)(s & 1) * 8u;
                    *(u64*)(Ah + soff) = (u64)lo | ((u64)hi << 32);
                }
            }

            cpa_wait0();                  // B[p] landed
            bar_arrive(1 + p, NTHREADS);  // signal full[p]
        }

        zp[s * 64 + ia] = zacc;
        __syncthreads();
    }
}

// ============================================================
extern "C" void kernel_launch(void* const* d_in, const int* in_sizes, int n_in,
                              void* d_out, int out_size) {
    (void)in_sizes; (void)n_in; (void)out_size;
    const float* x    = (const float*)d_in[0];
    const int*   adj  = (const int*)  d_in[1];
    const float* W    = (const float*)d_in[2];
    const float* a    = (const float*)d_in[3];
    const float* bias = (const float*)d_in[4];
    float* out = (float*)d_out;

    cudaFuncSetAttribute(k_xw_mma, cudaFuncAttributeMaxDynamicSharedMemorySize, XW_SMEM);
    cudaFuncSetAttribute(k_attn,   cudaFuncAttributeMaxDynamicSharedMemorySize, SMEM_ATTN);

    k_cvt   <<<2048, 256>>>(x, W);
    k_xw_mma<<<NN / 64, 256, XW_SMEM>>>();
    k_s     <<<NN / 8, 256>>>(a);
    k_attn  <<<NN / 64, NTHREADS, SMEM_ATTN>>>(adj, bias, out);
}

// round 9
// speedup vs baseline: 7.6263x; 1.2610x over previous
#include <cuda_runtime.h>
#include <cuda_fp16.h>
#include <cstdint>
#include <cstddef>

#define NN    8192
#define INF_  512
#define OUTF  256
#define ALPHA 0.2f

typedef unsigned long long u64;
typedef unsigned int u32;

// ---------------- scratch globals (no allocs allowed) ----------------
__device__ float g_h[NN * OUTF];
__device__ float g_s1[NN];
__device__ float g_s2[NN];
__device__ float g_e1p[NN];   // exp(s1)
__device__ float g_e1n[NN];   // exp(ALPHA*s1)
__device__ float g_e2p[NN];   // exp(s2)
__device__ float g_e2n[NN];   // exp(ALPHA*s2)
// h as fp16, PRE-SWIZZLED B-layout: byte(j,n) = j*512 + (((n>>3)^(j&7))<<4) + (n&7)*2
__device__ __align__(16) unsigned char g_hh[(size_t)NN * 512];
// x as fp16, PRE-SWIZZLED A-layout per 128-k tile
__device__ __align__(16) unsigned char g_xh[(size_t)NN * 1024];
// W as fp16, PRE-SWIZZLED B-layout per 128-k tile
__device__ __align__(16) unsigned char g_wh[(size_t)INF_ * 512];

// ---------------- mma / ldmatrix / cp.async / barrier helpers ----------------
__device__ __forceinline__ u32 smem_u32(const void* p) {
    u32 a;
    asm("{ .reg .u64 t; cvta.to.shared.u64 t, %1; cvt.u32.u64 %0, t; }"
        : "=r"(a) : "l"(p));
    return a;
}
__device__ __forceinline__ void ldsm4(u32* r, u32 addr) {
    asm volatile("ldmatrix.sync.aligned.m8n8.x4.shared.b16 {%0,%1,%2,%3}, [%4];"
                 : "=r"(r[0]), "=r"(r[1]), "=r"(r[2]), "=r"(r[3]) : "r"(addr));
}
__device__ __forceinline__ void ldsm4t(u32* r, u32 addr) {
    asm volatile("ldmatrix.sync.aligned.m8n8.x4.trans.shared.b16 {%0,%1,%2,%3}, [%4];"
                 : "=r"(r[0]), "=r"(r[1]), "=r"(r[2]), "=r"(r[3]) : "r"(addr));
}
__device__ __forceinline__ void mma16816(float* d, const u32* a, const u32* b) {
    asm volatile(
        "mma.sync.aligned.m16n8k16.row.col.f32.f16.f16.f32 "
        "{%0,%1,%2,%3}, {%4,%5,%6,%7}, {%8,%9}, {%0,%1,%2,%3};"
        : "+f"(d[0]), "+f"(d[1]), "+f"(d[2]), "+f"(d[3])
        : "r"(a[0]), "r"(a[1]), "r"(a[2]), "r"(a[3]), "r"(b[0]), "r"(b[1]));
}
__device__ __forceinline__ void cpa16(u32 dst, const void* src) {
    asm volatile("cp.async.cg.shared.global [%0], [%1], 16;"
                 :: "r"(dst), "l"(src) : "memory");
}
__device__ __forceinline__ void cpa_commit() {
    asm volatile("cp.async.commit_group;" ::: "memory");
}
__device__ __forceinline__ void cpa_wait0() {
    asm volatile("cp.async.wait_group 0;" ::: "memory");
}
__device__ __forceinline__ void cpa_wait1() {
    asm volatile("cp.async.wait_group 1;" ::: "memory");
}
__device__ __forceinline__ u32 packh2(float a, float b) {
    __half2 h = __floats2half2_rn(a, b);
    return *reinterpret_cast<u32*>(&h);
}
__device__ __forceinline__ void bar_sync(int id, int cnt) {
    asm volatile("bar.sync %0, %1;" :: "r"(id), "r"(cnt) : "memory");
}
__device__ __forceinline__ void bar_arrive(int id, int cnt) {
    asm volatile("bar.arrive %0, %1;" :: "r"(id), "r"(cnt) : "memory");
}

// ============================================================
// Kernel 0: convert x -> g_xh (A-layout) and W -> g_wh (B-layout)
// ============================================================
__global__ void __launch_bounds__(256) k_cvt(const float* __restrict__ x,
                                             const float* __restrict__ W) {
    int gid = blockIdx.x * 256 + threadIdx.x;     // 524288 total
    {
        int i = gid >> 6;
        int c = gid & 63;
        int ktile = c >> 4;
        int kc = c & 15;
        const float4* src = (const float4*)(x + (size_t)i * INF_ + c * 8);
        float4 a = src[0], b = src[1];
        uint4 o = make_uint4(packh2(a.x, a.y), packh2(a.z, a.w),
                             packh2(b.x, b.y), packh2(b.z, b.w));
        u32 off = (u32)ktile * 2097152u + (u32)i * 256u
                + ((((u32)kc) ^ ((u32)i & 7u)) << 4);
        *(uint4*)(g_xh + off) = o;
    }
    if (gid < 16384) {
        int k = gid >> 5;
        int c = gid & 31;
        int ktile = k >> 7, kl = k & 127;
        const float4* src = (const float4*)(W + (size_t)k * OUTF + c * 8);
        float4 a = src[0], b = src[1];
        uint4 o = make_uint4(packh2(a.x, a.y), packh2(a.z, a.w),
                             packh2(b.x, b.y), packh2(b.z, b.w));
        u32 off = (u32)ktile * 65536u + (u32)kl * 512u
                + ((((u32)c) ^ ((u32)kl & 7u)) << 4);
        *(uint4*)(g_wh + off) = o;
    }
}

// ============================================================
// Kernel 1: h = x @ W via fp16 mma.sync; writes g_h (fp32) + g_hh (fp16 swz)
// ============================================================
#define XW_SMA 0
#define XW_SMB 32768
#define XW_SMEM 163840

__global__ void __launch_bounds__(256) k_xw_mma() {
    extern __shared__ __align__(16) char smem[];
    const u32 sb = smem_u32(smem);
    const int tid  = threadIdx.x;
    const int lane = tid & 31;
    const int wid  = tid >> 5;
    const int wn   = wid & 3;
    const int wm   = wid >> 2;
    const int i0   = blockIdx.x * 64;

    float acc[2][8][4];
    #pragma unroll
    for (int mi = 0; mi < 2; mi++)
        #pragma unroll
        for (int n8 = 0; n8 < 8; n8++)
            #pragma unroll
            for (int c = 0; c < 4; c++) acc[mi][n8][c] = 0.f;

    #define XW_ISSUE(kt, bb)                                                     \
    {                                                                            \
        const u32 dstA = sb + XW_SMA + (u32)(bb) * 16384u;                       \
        const unsigned char* srcA = g_xh + (size_t)(kt) * 2097152 + (size_t)i0 * 256; \
        _Pragma("unroll")                                                        \
        for (int it = 0; it < 4; it++) {                                         \
            u32 off = (u32)tid * 16u + (u32)it * 4096u;                          \
            cpa16(dstA + off, srcA + off);                                       \
        }                                                                        \
        const u32 dstB = sb + XW_SMB + (u32)(bb) * 65536u;                       \
        const unsigned char* srcB = g_wh + (size_t)(kt) * 65536;                 \
        _Pragma("unroll")                                                        \
        for (int it = 0; it < 16; it++) {                                        \
            u32 off = (u32)tid * 16u + (u32)it * 4096u;                          \
            cpa16(dstB + off, srcB + off);                                       \
        }                                                                        \
        cpa_commit();                                                            \
    }

    XW_ISSUE(0, 0);

    const u32 a_row_off = (u32)((wm * 32 + (lane & 15)) * 256);
    const u32 a_hi      = (u32)(lane >> 4);
    const u32 sxor      = (u32)(lane & 7);
    const u32 b_row_off = (u32)((lane & 15) * 512 + wn * 128);

    for (int kt = 0; kt < 4; kt++) {
        const int buf = kt & 1;
        if (kt < 3) { XW_ISSUE(kt + 1, buf ^ 1); cpa_wait1(); }
        else        { cpa_wait0(); }
        __syncthreads();

        const u32 Abuf = sb + XW_SMA + (u32)buf * 16384u;
        const u32 Bbuf = sb + XW_SMB + (u32)buf * 65536u;
        #pragma unroll
        for (int kk = 0; kk < 8; kk++) {
            u32 afr[2][4];
            #pragma unroll
            for (int mi = 0; mi < 2; mi++) {
                u32 chunk = (u32)(kk * 2) + a_hi;
                ldsm4(afr[mi], Abuf + a_row_off + (u32)mi * 4096u
                                  + ((chunk ^ sxor) << 4));
            }
            u32 bfr[4][4];
            #pragma unroll
            for (int nb2 = 0; nb2 < 4; nb2++) {
                u32 chunk = (u32)(nb2 * 2) + a_hi;
                ldsm4t(bfr[nb2], Bbuf + (u32)(kk * 16) * 512u + b_row_off
                                    + ((chunk ^ sxor) << 4));
            }
            #pragma unroll
            for (int mi = 0; mi < 2; mi++)
                #pragma unroll
                for (int n8 = 0; n8 < 8; n8++)
                    mma16816(acc[mi][n8], afr[mi], &bfr[n8 >> 1][(n8 & 1) * 2]);
        }
        __syncthreads();
    }

    const int g  = lane >> 2;
    const int tq = lane & 3;
    #pragma unroll
    for (int mi = 0; mi < 2; mi++) {
        int rl0 = wm * 32 + mi * 16 + g;
        int j0r = i0 + rl0, j8r = i0 + rl0 + 8;
        #pragma unroll
        for (int n8 = 0; n8 < 8; n8++) {
            int col = wn * 64 + n8 * 8 + tq * 2;
            float2 h0 = make_float2(acc[mi][n8][0], acc[mi][n8][1]);
            float2 h8 = make_float2(acc[mi][n8][2], acc[mi][n8][3]);
            *(float2*)&g_h[(size_t)j0r * OUTF + col] = h0;
            *(float2*)&g_h[(size_t)j8r * OUTF + col] = h8;
            u32 off0 = (u32)j0r * 512u + ((((u32)(col >> 3)) ^ ((u32)j0r & 7u)) << 4)
                     + ((u32)(col & 7)) * 2u;
            u32 off8 = (u32)j8r * 512u + ((((u32)(col >> 3)) ^ ((u32)j8r & 7u)) << 4)
                     + ((u32)(col & 7)) * 2u;
            *(u32*)(g_hh + off0) = packh2(h0.x, h0.y);
            *(u32*)(g_hh + off8) = packh2(h8.x, h8.y);
        }
    }
    #undef XW_ISSUE
}

// ============================================================
// Kernel 2: s1/s2 + factorized exp tables
// ============================================================
__global__ void __launch_bounds__(256) k_s(const float* __restrict__ a) {
    int row  = blockIdx.x * 8 + (threadIdx.x >> 5);
    int lane = threadIdx.x & 31;
    const float* hr = g_h + (size_t)row * OUTF;
    float p1 = 0.f, p2 = 0.f;
    #pragma unroll
    for (int c = lane; c < OUTF; c += 32) {
        float hv = hr[c];
        p1 += hv * a[c];
        p2 += hv * a[OUTF + c];
    }
    #pragma unroll
    for (int off = 16; off; off >>= 1) {
        p1 += __shfl_xor_sync(0xffffffffu, p1, off);
        p2 += __shfl_xor_sync(0xffffffffu, p2, off);
    }
    if (lane == 0) {
        g_s1[row]  = p1;
        g_s2[row]  = p2;
        g_e1p[row] = __expf(p1);
        g_e1n[row] = __expf(ALPHA * p1);
        g_e2p[row] = __expf(p2);
        g_e2n[row] = __expf(ALPHA * p2);
    }
}

// ============================================================
// Kernel 3: warp-specialized fused masked-softmax + P@h
//   512 threads: warps 0-7 consumers (MMA), warps 8-15 producers.
//   Producer thread = 4 rows x 8 contiguous j (octet): 6 table LDG +
//   8 adj LDG + 4 STS.128 per tile (2.1x fewer LSU ops than R8).
// ============================================================
#define KT 128
#define NTILE (NN / KT)
// smem: zp[16][64] floats @0 (4KB); A @4096 (2 x 16KB); B @36864 (2 x 64KB)
#define SM_ZP   0
#define SM_A    4096
#define SM_B    36864
#define SMEM_ATTN 167936
#define NTHREADS 512

__global__ void __launch_bounds__(NTHREADS) k_attn(const int* __restrict__ adj,
                                                   const float* __restrict__ bias,
                                                   float* __restrict__ out) {
    extern __shared__ __align__(16) char smem[];
    const u32 sb = smem_u32(smem);
    const int tid  = threadIdx.x;
    const int lane = tid & 31;
    const int wid  = tid >> 5;
    const int i0   = blockIdx.x * 64;
    float* zp = (float*)(smem + SM_ZP);    // zp[oct][row] = [16][64]

    if (wid < 8) {
        // ================= CONSUMERS: MMA =================
        const int wn = wid & 3;
        const int wm = wid >> 2;

        float acc[2][8][4];
        #pragma unroll
        for (int mi = 0; mi < 2; mi++)
            #pragma unroll
            for (int n8 = 0; n8 < 8; n8++)
                #pragma unroll
                for (int c = 0; c < 4; c++) acc[mi][n8][c] = 0.f;

        const u32 a_row_off = (u32)((wm * 32 + (lane & 15)) * 256);
        const u32 a_hi      = (u32)(lane >> 4);
        const u32 sxor      = (u32)(lane & 7);
        const u32 b_row_off = (u32)((lane & 15) * 512 + wn * 128);

        for (int t = 0; t < NTILE; t++) {
            const int p = t & 1;
            bar_sync(1 + p, NTHREADS);   // wait full[p]

            const u32 Abuf = sb + SM_A + (u32)p * 16384u;
            const u32 Bbuf = sb + SM_B + (u32)p * 65536u;
            #pragma unroll
            for (int kk = 0; kk < 8; kk++) {
                u32 afr[2][4];
                #pragma unroll
                for (int mi = 0; mi < 2; mi++) {
                    u32 chunk = (u32)(kk * 2) + a_hi;
                    ldsm4(afr[mi], Abuf + a_row_off + (u32)mi * 4096u
                                      + ((chunk ^ sxor) << 4));
                }
                u32 bfr[4][4];
                #pragma unroll
                for (int nb2 = 0; nb2 < 4; nb2++) {
                    u32 chunk = (u32)(nb2 * 2) + a_hi;
                    ldsm4t(bfr[nb2], Bbuf + (u32)(kk * 16) * 512u + b_row_off
                                        + ((chunk ^ sxor) << 4));
                }
                #pragma unroll
                for (int mi = 0; mi < 2; mi++)
                    #pragma unroll
                    for (int n8 = 0; n8 < 8; n8++)
                        mma16816(acc[mi][n8], afr[mi], &bfr[n8 >> 1][(n8 & 1) * 2]);
            }
            bar_arrive(3 + p, NTHREADS); // signal empty[p]
        }

        __syncthreads();   // producers have written zp

        // ---- epilogue: out = acc/Z + bias (Z = sum of 16 octet partials) ----
        const int g  = lane >> 2;
        const int tq = lane & 3;
        #pragma unroll
        for (int mi = 0; mi < 2; mi++) {
            int rl0 = wm * 32 + mi * 16 + g;
            float z0 = 0.f, z8 = 0.f;
            #pragma unroll
            for (int o = 0; o < 16; o++) {
                z0 += zp[o * 64 + rl0];
                z8 += zp[o * 64 + rl0 + 8];
            }
            float inv0 = (z0 > 0.f) ? 1.0f / z0 : 0.f;
            float inv8 = (z8 > 0.f) ? 1.0f / z8 : 0.f;
            float* o0 = out + (size_t)(i0 + rl0) * OUTF;
            float* o8 = out + (size_t)(i0 + rl0 + 8) * OUTF;
            #pragma unroll
            for (int n8 = 0; n8 < 8; n8++) {
                int col = wn * 64 + n8 * 8 + tq * 2;
                float2 b2 = *(const float2*)(bias + col);
                float2 r0, r8;
                r0.x = acc[mi][n8][0] * inv0 + b2.x;
                r0.y = acc[mi][n8][1] * inv0 + b2.y;
                r8.x = acc[mi][n8][2] * inv8 + b2.x;
                r8.y = acc[mi][n8][3] * inv8 + b2.y;
                *(float2*)(o0 + col) = r0;
                *(float2*)(o8 + col) = r8;
            }
        }
    } else {
        // ================= PRODUCERS: fetch + pack =================
        const int ptid = tid - 256;        // 0..255
        const int oct  = ptid & 15;        // j-octet: j = oct*8 .. +7
        const int rg   = ptid >> 4;        // row group: rows rg*4 .. +3
        float s1v[4], e1pv[4], e1nv[4], zacc[4];
        #pragma unroll
        for (int rr = 0; rr < 4; rr++) {
            int i = rg * 4 + rr;
            s1v[rr]  = g_s1[i0 + i];
            e1pv[rr] = g_e1p[i0 + i];
            e1nv[rr] = g_e1n[i0 + i];
            zacc[rr] = 0.f;
        }

        for (int tp = 0; tp < NTILE; tp++) {
            const int p = tp & 1;
            if (tp >= 2) bar_sync(3 + p, NTHREADS);   // wait empty[p]

            // ---- issue B cp.async (64KB pre-swizzled fp16 h) ----
            {
                const u32 dstB = sb + SM_B + (u32)p * 65536u;
                const unsigned char* src = g_hh + (size_t)tp * 65536 + ptid * 16;
                #pragma unroll
                for (int it = 0; it < 16; it++)
                    cpa16(dstB + (u32)ptid * 16u + (u32)it * 4096u, src + it * 4096);
                cpa_commit();
            }

            // ---- pack P tile: 4 rows x 8 j per thread ----
            {
                const int jb = tp * KT + oct * 8;
                // tables for this octet (shared by all 4 rows)
                float4 s2a = *(const float4*)(g_s2  + jb);
                float4 s2b = *(const float4*)(g_s2  + jb + 4);
                float4 epa = *(const float4*)(g_e2p + jb);
                float4 epb = *(const float4*)(g_e2p + jb + 4);
                float4 ena = *(const float4*)(g_e2n + jb);
                float4 enb = *(const float4*)(g_e2n + jb + 4);
                char* Ah = smem + SM_A + p * 16384;
                #pragma unroll
                for (int rr = 0; rr < 4; rr++) {
                    int i = rg * 4 + rr;
                    const int* ar = adj + (size_t)(i0 + i) * NN + jb;
                    int4 a0 = *(const int4*)ar;
                    int4 a1 = *(const int4*)(ar + 4);
                    float s1 = s1v[rr], ep = e1pv[rr], en = e1nv[rr];
                    float p0 = (a0.x > 0) ? ((s1 + s2a.x > 0.f) ? ep * epa.x : en * ena.x) : 0.f;
                    float p1 = (a0.y > 0) ? ((s1 + s2a.y > 0.f) ? ep * epa.y : en * ena.y) : 0.f;
                    float p2 = (a0.z > 0) ? ((s1 + s2a.z > 0.f) ? ep * epa.z : en * ena.z) : 0.f;
                    float p3 = (a0.w > 0) ? ((s1 + s2a.w > 0.f) ? ep * epa.w : en * ena.w) : 0.f;
                    float p4 = (a1.x > 0) ? ((s1 + s2b.x > 0.f) ? ep * epb.x : en * enb.x) : 0.f;
                    float p5 = (a1.y > 0) ? ((s1 + s2b.y > 0.f) ? ep * epb.y : en * enb.y) : 0.f;
                    float p6 = (a1.z > 0) ? ((s1 + s2b.z > 0.f) ? ep * epb.z : en * enb.z) : 0.f;
                    float p7 = (a1.w > 0) ? ((s1 + s2b.w > 0.f) ? ep * epb.w : en * enb.w) : 0.f;
                    zacc[rr] += ((p0 + p1) + (p2 + p3)) + ((p4 + p5) + (p6 + p7));
                    uint4 o = make_uint4(packh2(p0, p1), packh2(p2, p3),
                                         packh2(p4, p5), packh2(p6, p7));
                    u32 soff = (u32)i * 256u + ((((u32)oct) ^ ((u32)i & 7u)) << 4);
                    *(uint4*)(Ah + soff) = o;
                }
            }

            cpa_wait0();                  // B[p] landed
            bar_arrive(1 + p, NTHREADS);  // signal full[p]
        }

        #pragma unroll
        for (int rr = 0; rr < 4; rr++)
            zp[oct * 64 + rg * 4 + rr] = zacc[rr];
        __syncthreads();
    }
}

// ============================================================
extern "C" void kernel_launch(void* const* d_in, const int* in_sizes, int n_in,
                              void* d_out, int out_size) {
    (void)in_sizes; (void)n_in; (void)out_size;
    const float* x    = (const float*)d_in[0];
    const int*   adj  = (const int*)  d_in[1];
    const float* W    = (const float*)d_in[2];
    const float* a    = (const float*)d_in[3];
    const float* bias = (const float*)d_in[4];
    float* out = (float*)d_out;

    cudaFuncSetAttribute(k_xw_mma, cudaFuncAttributeMaxDynamicSharedMemorySize, XW_SMEM);
    cudaFuncSetAttribute(k_attn,   cudaFuncAttributeMaxDynamicSharedMemorySize, SMEM_ATTN);

    k_cvt   <<<2048, 256>>>(x, W);
    k_xw_mma<<<NN / 64, 256, XW_SMEM>>>();
    k_s     <<<NN / 8, 256>>>(a);
    k_attn  <<<NN / 64, NTHREADS, SMEM_ATTN>>>(adj, bias, out);
}